// round 7
// baseline (speedup 1.0000x reference)
#include <cuda_runtime.h>
#include <cuda_fp16.h>
#include <math.h>

#define N_NODES 50000
#define N_EDGES 800000
#define NFEAT 128
#define NHID 96
#define NCLASS 64
#define NEXT 32
#define BN_EPS 1e-5f

#define SCAN_B 512
#define NB_SCAN ((N_NODES + SCAN_B - 1) / SCAN_B)   // 98

// ---------------- scratch (device globals; zero-initialized at load) --------
// Invariant at entry/exit of every call: g_cnt == 0, g_pool == 0, g_done == 0.
__device__ __align__(16) __half g_support1h[N_NODES * NHID];   // x@W1 (fp16)
__device__ __align__(16) float  g_h1[N_NODES * NHID];          // selu(agg1+b1)
__device__ __align__(16) __half g_support2h[N_NODES * NCLASS]; // h1@W2 (fp16)
__device__ float g_pool[NCLASS];
__device__ int   g_done;

__device__ int  g_cnt[N_NODES];
__device__ int  g_off[N_NODES + 1];
__device__ int  g_cur[N_NODES];
__device__ int  g_partial[NB_SCAN];
__device__ int2 g_es[N_EDGES];

// ---------------- helpers ----------------------------------------------------
__device__ __forceinline__ float selu_f(float v) {
    const float scale = 1.0507009873554805f;
    const float alpha = 1.6732632423543772f;
    return scale * (v > 0.0f ? v : alpha * (expf(v) - 1.0f));
}

__device__ __forceinline__ unsigned f2tf32(float f) {
    unsigned u;
    asm("cvt.rna.tf32.f32 %0, %1;" : "=r"(u) : "f"(f));
    return u;
}

__device__ __forceinline__ void mma_tf32(float c[4], const unsigned a[4],
                                         const unsigned b[2]) {
    asm volatile(
        "mma.sync.aligned.m16n8k8.row.col.f32.tf32.tf32.f32 "
        "{%0,%1,%2,%3}, {%4,%5,%6,%7}, {%8,%9}, {%0,%1,%2,%3};"
        : "+f"(c[0]), "+f"(c[1]), "+f"(c[2]), "+f"(c[3])
        : "r"(a[0]), "r"(a[1]), "r"(a[2]), "r"(a[3]), "r"(b[0]), "r"(b[1]));
}

// ---------------- K1: histogram ----------------------------------------------
__global__ void hist_kernel(const int* __restrict__ row, int E) {
    int e = blockIdx.x * blockDim.x + threadIdx.x;
    if (e < E) atomicAdd(&g_cnt[row[e]], 1);
}

// ---------------- K2: per-block exclusive scan of degrees --------------------
__global__ __launch_bounds__(SCAN_B)
void scanA_kernel() {
    __shared__ int s[SCAN_B];
    int t = threadIdx.x, b = blockIdx.x;
    int i = b * SCAN_B + t;
    int v = (i < N_NODES) ? g_cnt[i] : 0;
    s[t] = v;
    __syncthreads();
    for (int d = 1; d < SCAN_B; d <<= 1) {
        int x = (t >= d) ? s[t - d] : 0;
        __syncthreads();
        s[t] += x;
        __syncthreads();
    }
    if (i < N_NODES) g_off[i] = s[t] - v;
    if (t == SCAN_B - 1) g_partial[b] = s[t];
}

// ---------------- K3: apply top-level scan + init cursors --------------------
__global__ __launch_bounds__(256)
void scanBC_kernel() {
    __shared__ int p[128];
    int t = threadIdx.x;
    p[t & 127] = 0;
    __syncthreads();
    if (t < NB_SCAN) p[t] = g_partial[t];
    __syncthreads();
    for (int d = 1; d < 128; d <<= 1) {
        int x = (t < 128 && t >= d) ? p[t - d] : 0;
        __syncthreads();
        if (t < 128) p[t] += x;
        __syncthreads();
    }
    int i = blockIdx.x * 256 + t;
    if (i < N_NODES) {
        int s = i >> 9;
        int base = (s == 0) ? 0 : p[s - 1];
        int o = g_off[i] + base;
        g_off[i] = o;
        g_cur[i] = o;
    }
    if (blockIdx.x == 0 && t == 0) g_off[N_NODES] = p[NB_SCAN - 1];
}

// ---------------- tf32 tensor-core GEMM tile, fp16 output --------------------
// C[M,N](half) = A[M,K](f32) @ W[K,N](f32). BM=64, BK=32.
// 256 thr = 8 warps as 4(m) x 2(n); warp tile 16 x NT*8. acc = NT*4 regs.
// As[32][72]  (bank stride 8: conflict-free fragment loads)
// Bs[N][36]   (bank stride 4: conflict-free fragment loads)
template <int K, int N, int NT>
__device__ __forceinline__
void gemm_tf32(const float* __restrict__ A, const float* __restrict__ W,
               __half* __restrict__ C, int M, int m0) {
    __shared__ unsigned As[32][72];
    __shared__ unsigned Bs[N][36];

    const int t = threadIdx.x;
    const int lane = t & 31;
    const int wid = t >> 5;
    const int warp_m = wid >> 1;        // 0..3 -> 16 rows each
    const int warp_n = wid & 1;         // 0..1
    const int lq = lane >> 2;           // 0..7
    const int lr = lane & 3;            // 0..3

    float acc[NT][4];
#pragma unroll
    for (int j = 0; j < NT; j++)
#pragma unroll
        for (int q = 0; q < 4; q++) acc[j][q] = 0.f;

    const int arow = t >> 2;            // 0..63
    const int aq0 = (t & 3) * 2;        // float4 slot base (2 per thread)

    for (int kk = 0; kk < K; kk += 32) {
        // stage A tile [64 x 32] -> As[k][m]
#pragma unroll
        for (int q = 0; q < 2; q++) {
            int kq = (aq0 + q) * 4;
            float4 v = make_float4(0.f, 0.f, 0.f, 0.f);
            if (m0 + arow < M)
                v = *reinterpret_cast<const float4*>(A + (size_t)(m0 + arow) * K + kk + kq);
            As[kq + 0][arow] = f2tf32(v.x);
            As[kq + 1][arow] = f2tf32(v.y);
            As[kq + 2][arow] = f2tf32(v.z);
            As[kq + 3][arow] = f2tf32(v.w);
        }
        // stage W tile [32 x N] -> Bs[n][k]
        for (int i = t; i < 32 * N; i += 256) {
            int k = i / N;
            int n = i - k * N;
            Bs[n][k] = f2tf32(W[(size_t)(kk + k) * N + n]);
        }
        __syncthreads();

#pragma unroll
        for (int ks = 0; ks < 4; ks++) {
            const int k8 = ks * 8;
            unsigned b[NT][2];
            const int bn = warp_n * (NT * 8) + lq;
#pragma unroll
            for (int j = 0; j < NT; j++) {
                b[j][0] = Bs[bn + j * 8][k8 + lr];
                b[j][1] = Bs[bn + j * 8][k8 + lr + 4];
            }
            unsigned a[4];
            const int r = warp_m * 16 + lq;
            a[0] = As[k8 + lr][r];
            a[1] = As[k8 + lr][r + 8];
            a[2] = As[k8 + lr + 4][r];
            a[3] = As[k8 + lr + 4][r + 8];
#pragma unroll
            for (int j = 0; j < NT; j++) mma_tf32(acc[j], a, b[j]);
        }
        __syncthreads();
    }

    // epilogue -> fp16: c0,c1 at (r, 2lr),(r, 2lr+1); c2,c3 at (r+8, ...)
    int r0 = m0 + warp_m * 16 + lq;
#pragma unroll
    for (int j = 0; j < NT; j++) {
        int c0 = warp_n * (NT * 8) + j * 8 + 2 * lr;
        if (r0 < M)
            *reinterpret_cast<__half2*>(C + (size_t)r0 * N + c0) =
                __floats2half2_rn(acc[j][0], acc[j][1]);
        if (r0 + 8 < M)
            *reinterpret_cast<__half2*>(C + (size_t)(r0 + 8) * N + c0) =
                __floats2half2_rn(acc[j][2], acc[j][3]);
    }
}

// ---------------- K4: fat kernel — gemm1(tf32) || scatter || zero g_cnt ------
__global__ __launch_bounds__(256)
void fat1_kernel(const float* __restrict__ x, const float* __restrict__ W1,
                 const int* __restrict__ row, const int* __restrict__ col,
                 const float* __restrict__ ew, int E, int GB, int SCB) {
    int bid = blockIdx.x;
    int t = threadIdx.x;

    if (bid < GB) {
        gemm_tf32<NFEAT, NHID, 6>(x, W1, g_support1h, N_NODES, bid * 64);
    } else if (bid < GB + SCB) {
        int base = ((bid - GB) * 256 + t) * 4;
#pragma unroll
        for (int u = 0; u < 4; u++) {
            int e = base + u;
            if (e < E) {
                int p = atomicAdd(&g_cur[row[e]], 1);
                int2 packed;
                packed.x = col[e];
                packed.y = __float_as_int(ew[e]);
                g_es[p] = packed;
            }
        }
    } else {
        int base = ((bid - GB - SCB) * 256 + t) * 4;
#pragma unroll
        for (int u = 0; u < 4; u++) {
            int i = base + u;
            if (i < N_NODES) g_cnt[i] = 0;
        }
    }
}

// ---------------- K5: CSR SpMM layer 1 (fp16 gather) + bias + SELU -----------
// CH = 24 chunks of 4 halves per node; 24 threads per node.
__global__ __launch_bounds__(192)
void spmm1_kernel(const float* __restrict__ b1) {
    constexpr int CH = NHID / 4;
    int idx = blockIdx.x * 192 + threadIdx.x;
    int n = idx / CH;
    int c = idx - n * CH;
    if (n >= N_NODES) return;
    int off = g_off[n];
    int deg = g_off[n + 1] - off;
    const uint2* sup = reinterpret_cast<const uint2*>(g_support1h);

    float4 acc = make_float4(0.f, 0.f, 0.f, 0.f);
    int j = 0;
    for (; j + 3 < deg; j += 4) {
        int2 e0 = g_es[off + j];
        int2 e1 = g_es[off + j + 1];
        int2 e2 = g_es[off + j + 2];
        int2 e3 = g_es[off + j + 3];
        uint2 u0 = sup[(size_t)e0.x * CH + c];
        uint2 u1 = sup[(size_t)e1.x * CH + c];
        uint2 u2 = sup[(size_t)e2.x * CH + c];
        uint2 u3 = sup[(size_t)e3.x * CH + c];
        float w0 = __int_as_float(e0.y), w1 = __int_as_float(e1.y);
        float w2 = __int_as_float(e2.y), w3 = __int_as_float(e3.y);
        float2 a0 = __half22float2(*reinterpret_cast<__half2*>(&u0.x));
        float2 b0 = __half22float2(*reinterpret_cast<__half2*>(&u0.y));
        float2 a1 = __half22float2(*reinterpret_cast<__half2*>(&u1.x));
        float2 b1v = __half22float2(*reinterpret_cast<__half2*>(&u1.y));
        float2 a2 = __half22float2(*reinterpret_cast<__half2*>(&u2.x));
        float2 b2v = __half22float2(*reinterpret_cast<__half2*>(&u2.y));
        float2 a3 = __half22float2(*reinterpret_cast<__half2*>(&u3.x));
        float2 b3v = __half22float2(*reinterpret_cast<__half2*>(&u3.y));
        acc.x += w0 * a0.x + w1 * a1.x + w2 * a2.x + w3 * a3.x;
        acc.y += w0 * a0.y + w1 * a1.y + w2 * a2.y + w3 * a3.y;
        acc.z += w0 * b0.x + w1 * b1v.x + w2 * b2v.x + w3 * b3v.x;
        acc.w += w0 * b0.y + w1 * b1v.y + w2 * b2v.y + w3 * b3v.y;
    }
    for (; j < deg; j++) {
        int2 e0 = g_es[off + j];
        float w0 = __int_as_float(e0.y);
        uint2 u0 = sup[(size_t)e0.x * CH + c];
        float2 a0 = __half22float2(*reinterpret_cast<__half2*>(&u0.x));
        float2 b0 = __half22float2(*reinterpret_cast<__half2*>(&u0.y));
        acc.x += w0 * a0.x;
        acc.y += w0 * a0.y;
        acc.z += w0 * b0.x;
        acc.w += w0 * b0.y;
    }
    float4 bb = reinterpret_cast<const float4*>(b1)[c];
    float4 r;
    r.x = selu_f(acc.x + bb.x);
    r.y = selu_f(acc.y + bb.y);
    r.z = selu_f(acc.z + bb.z);
    r.w = selu_f(acc.w + bb.w);
    reinterpret_cast<float4*>(g_h1)[(size_t)n * CH + c] = r;
}

// ---------------- K6: GEMM layer 2 (tf32, fp16 out) --------------------------
__global__ __launch_bounds__(256)
void gemm2_kernel(const float* __restrict__ W2) {
    gemm_tf32<NHID, NCLASS, 4>(g_h1, W2, g_support2h, N_NODES, blockIdx.x * 64);
}

// ---------------- K7: SpMM layer 2 (fp16) + selu + pool + tail-block head ----
__global__ __launch_bounds__(256)
void spmm2_final_kernel(const float* __restrict__ b2,
                        const float* __restrict__ sub, const float* __restrict__ Wf,
                        const float* __restrict__ bf, const float* __restrict__ gamma,
                        const float* __restrict__ beta, const float* __restrict__ mean,
                        const float* __restrict__ var, float* __restrict__ out) {
    constexpr int CH = NCLASS / 4;
    __shared__ float sp[NCLASS];
    __shared__ int s_last;
    int t = threadIdx.x;
    if (t < NCLASS) sp[t] = 0.f;
    __syncthreads();

    int idx = blockIdx.x * 256 + t;
    int n = idx / CH;
    int c = idx - n * CH;
    float4 r = make_float4(0.f, 0.f, 0.f, 0.f);

    if (n < N_NODES) {
        int off = g_off[n];
        int deg = g_off[n + 1] - off;
        const uint2* sup = reinterpret_cast<const uint2*>(g_support2h);
        float4 acc = make_float4(0.f, 0.f, 0.f, 0.f);
        int j = 0;
        for (; j + 3 < deg; j += 4) {
            int2 e0 = g_es[off + j];
            int2 e1 = g_es[off + j + 1];
            int2 e2 = g_es[off + j + 2];
            int2 e3 = g_es[off + j + 3];
            uint2 u0 = sup[(size_t)e0.x * CH + c];
            uint2 u1 = sup[(size_t)e1.x * CH + c];
            uint2 u2 = sup[(size_t)e2.x * CH + c];
            uint2 u3 = sup[(size_t)e3.x * CH + c];
            float w0 = __int_as_float(e0.y), w1 = __int_as_float(e1.y);
            float w2 = __int_as_float(e2.y), w3 = __int_as_float(e3.y);
            float2 a0 = __half22float2(*reinterpret_cast<__half2*>(&u0.x));
            float2 b0 = __half22float2(*reinterpret_cast<__half2*>(&u0.y));
            float2 a1 = __half22float2(*reinterpret_cast<__half2*>(&u1.x));
            float2 b1v = __half22float2(*reinterpret_cast<__half2*>(&u1.y));
            float2 a2 = __half22float2(*reinterpret_cast<__half2*>(&u2.x));
            float2 b2v = __half22float2(*reinterpret_cast<__half2*>(&u2.y));
            float2 a3 = __half22float2(*reinterpret_cast<__half2*>(&u3.x));
            float2 b3v = __half22float2(*reinterpret_cast<__half2*>(&u3.y));
            acc.x += w0 * a0.x + w1 * a1.x + w2 * a2.x + w3 * a3.x;
            acc.y += w0 * a0.y + w1 * a1.y + w2 * a2.y + w3 * a3.y;
            acc.z += w0 * b0.x + w1 * b1v.x + w2 * b2v.x + w3 * b3v.x;
            acc.w += w0 * b0.y + w1 * b1v.y + w2 * b2v.y + w3 * b3v.y;
        }
        for (; j < deg; j++) {
            int2 e0 = g_es[off + j];
            float w0 = __int_as_float(e0.y);
            uint2 u0 = sup[(size_t)e0.x * CH + c];
            float2 a0 = __half22float2(*reinterpret_cast<__half2*>(&u0.x));
            float2 b0 = __half22float2(*reinterpret_cast<__half2*>(&u0.y));
            acc.x += w0 * a0.x;
            acc.y += w0 * a0.y;
            acc.z += w0 * b0.x;
            acc.w += w0 * b0.y;
        }
        float4 bb = reinterpret_cast<const float4*>(b2)[c];
        r.x = selu_f(acc.x + bb.x);
        r.y = selu_f(acc.y + bb.y);
        r.z = selu_f(acc.z + bb.z);
        r.w = selu_f(acc.w + bb.w);
    }

    r.x += __shfl_xor_sync(0xffffffffu, r.x, 16);
    r.y += __shfl_xor_sync(0xffffffffu, r.y, 16);
    r.z += __shfl_xor_sync(0xffffffffu, r.z, 16);
    r.w += __shfl_xor_sync(0xffffffffu, r.w, 16);
    if ((t & 16) == 0) {
        atomicAdd(&sp[c * 4 + 0], r.x);
        atomicAdd(&sp[c * 4 + 1], r.y);
        atomicAdd(&sp[c * 4 + 2], r.z);
        atomicAdd(&sp[c * 4 + 3], r.w);
    }
    __syncthreads();
    if (t < NCLASS) atomicAdd(&g_pool[t], sp[t]);

    __threadfence();
    __syncthreads();
    if (t == 0) s_last = (atomicAdd(&g_done, 1) == (int)gridDim.x - 1);
    __syncthreads();
    if (!s_last) return;
    __threadfence();

    __shared__ float z[NCLASS + NEXT];
    __shared__ float logits[NCLASS];
    __shared__ float red[256];
    __shared__ float s_max, s_lse;

    if (t < NCLASS) {
        z[t] = selu_f(__ldcg(&g_pool[t]) / (float)N_NODES);
    } else if (t < NCLASS + NEXT) {
        int jj = t - NCLASS;
        z[t] = (sub[jj] - mean[jj]) * rsqrtf(var[jj] + BN_EPS) * gamma[jj] + beta[jj];
    }
    __syncthreads();

    if (t < NCLASS) {
        float a = bf[t];
        const float* wrow = Wf + (size_t)t * (NCLASS + NEXT);
#pragma unroll
        for (int k = 0; k < NCLASS + NEXT; k++) a += z[k] * wrow[k];
        logits[t] = a;
    }
    __syncthreads();

    if (t == 0) {
        float m = -INFINITY;
        for (int k = 0; k < NCLASS; k++) m = fmaxf(m, logits[k]);
        float s = 0.f;
        for (int k = 0; k < NCLASS; k++) s += expf(logits[k] - m);
        s_max = m;
        s_lse = logf(s);
    }
    __syncthreads();
    if (t < NCLASS) out[t] = logits[t] - s_max - s_lse;

    float l = 0.f;
    const int TOTW = NCLASS * (NCLASS + NEXT);
    for (int i = t; i < TOTW; i += 256) l += fabsf(Wf[i]);
    red[t] = l;
    __syncthreads();
    for (int s2 = 128; s2 > 0; s2 >>= 1) {
        if (t < s2) red[t] += red[t + s2];
        __syncthreads();
    }
    if (t == 0) out[NCLASS] = red[0] / (float)TOTW;

    if (t < NCLASS) g_pool[t] = 0.f;
    if (t == 0) g_done = 0;
}

// ---------------- launch -----------------------------------------------------
extern "C" void kernel_launch(void* const* d_in, const int* in_sizes, int n_in,
                              void* d_out, int out_size) {
    const float* x     = (const float*)d_in[0];
    const int*   row   = (const int*)  d_in[1];
    const int*   col   = (const int*)  d_in[2];
    const float* ew    = (const float*)d_in[3];
    const float* sub   = (const float*)d_in[4];
    const float* W1    = (const float*)d_in[5];
    const float* b1    = (const float*)d_in[6];
    const float* W2    = (const float*)d_in[7];
    const float* b2    = (const float*)d_in[8];
    const float* Wf    = (const float*)d_in[9];
    const float* bf    = (const float*)d_in[10];
    const float* gamma = (const float*)d_in[11];
    const float* beta  = (const float*)d_in[12];
    const float* mean  = (const float*)d_in[13];
    const float* var   = (const float*)d_in[14];
    float* out = (float*)d_out;

    const int E = (n_in > 1) ? in_sizes[1] : N_EDGES;

    const int GB  = (N_NODES + 63) / 64;     // 782 gemm blocks (BM=64)
    const int SCB = (E + 1023) / 1024;       // scatter blocks
    const int ZB  = (N_NODES + 1023) / 1024; // zero blocks

    hist_kernel<<<(E + 255) / 256, 256>>>(row, E);
    scanA_kernel<<<NB_SCAN, SCAN_B>>>();
    scanBC_kernel<<<(N_NODES + 255) / 256, 256>>>();
    fat1_kernel<<<GB + SCB + ZB, 256>>>(x, W1, row, col, ew, E, GB, SCB);
    spmm1_kernel<<<(N_NODES * (NHID / 4) + 191) / 192, 192>>>(b1);
    gemm2_kernel<<<GB, 256>>>(W2);
    spmm2_final_kernel<<<(N_NODES * (NCLASS / 4) + 255) / 256, 256>>>(
        b2, sub, Wf, bf, gamma, beta, mean, var, out);
}

// round 8
// speedup vs baseline: 1.1275x; 1.1275x over previous
#include <cuda_runtime.h>
#include <cuda_fp16.h>
#include <math.h>

#define N_NODES 50000
#define N_EDGES 800000
#define NFEAT 128
#define NHID 96
#define NCLASS 64
#define NEXT 32
#define BN_EPS 1e-5f

#define SCAN_B 512
#define NB_SCAN ((N_NODES + SCAN_B - 1) / SCAN_B)   // 98

// ---------------- scratch (device globals; zero-initialized at load) --------
// Invariant at entry/exit of every call: g_cnt == 0, g_pool == 0, g_done == 0.
__device__ __align__(16) __half g_support1h[N_NODES * NHID];   // x@W1 (fp16)
__device__ __align__(16) float  g_h1[N_NODES * NHID];          // selu(agg1+b1)
__device__ __align__(16) __half g_support2h[N_NODES * NCLASS]; // h1@W2 (fp16)
__device__ float g_pool[NCLASS];
__device__ int   g_done;

__device__ int  g_cnt[N_NODES];
__device__ int  g_off[N_NODES + 1];
__device__ int  g_cur[N_NODES];
__device__ int  g_partial[NB_SCAN];
__device__ int2 g_es[N_EDGES];

// ---------------- helpers ----------------------------------------------------
__device__ __forceinline__ float selu_f(float v) {
    const float scale = 1.0507009873554805f;
    const float alpha = 1.6732632423543772f;
    return scale * (v > 0.0f ? v : alpha * (expf(v) - 1.0f));
}

__device__ __forceinline__ unsigned f2tf32(float f) {
    unsigned u;
    asm("cvt.rna.tf32.f32 %0, %1;" : "=r"(u) : "f"(f));
    return u;
}

__device__ __forceinline__ void mma_tf32(float c[4], const unsigned a[4],
                                         const unsigned b[2]) {
    asm volatile(
        "mma.sync.aligned.m16n8k8.row.col.f32.tf32.tf32.f32 "
        "{%0,%1,%2,%3}, {%4,%5,%6,%7}, {%8,%9}, {%0,%1,%2,%3};"
        : "+f"(c[0]), "+f"(c[1]), "+f"(c[2]), "+f"(c[3])
        : "r"(a[0]), "r"(a[1]), "r"(a[2]), "r"(a[3]), "r"(b[0]), "r"(b[1]));
}

// ---------------- K1: histogram ----------------------------------------------
__global__ void hist_kernel(const int* __restrict__ row, int E) {
    int e = blockIdx.x * blockDim.x + threadIdx.x;
    if (e < E) atomicAdd(&g_cnt[row[e]], 1);
}

// ---------------- K2: per-block exclusive scan of degrees --------------------
__global__ __launch_bounds__(SCAN_B)
void scanA_kernel() {
    __shared__ int s[SCAN_B];
    int t = threadIdx.x, b = blockIdx.x;
    int i = b * SCAN_B + t;
    int v = (i < N_NODES) ? g_cnt[i] : 0;
    s[t] = v;
    __syncthreads();
    for (int d = 1; d < SCAN_B; d <<= 1) {
        int x = (t >= d) ? s[t - d] : 0;
        __syncthreads();
        s[t] += x;
        __syncthreads();
    }
    if (i < N_NODES) g_off[i] = s[t] - v;
    if (t == SCAN_B - 1) g_partial[b] = s[t];
}

// ---------------- K3: apply top-level scan + init cursors --------------------
__global__ __launch_bounds__(256)
void scanBC_kernel() {
    __shared__ int p[128];
    int t = threadIdx.x;
    p[t & 127] = 0;
    __syncthreads();
    if (t < NB_SCAN) p[t] = g_partial[t];
    __syncthreads();
    for (int d = 1; d < 128; d <<= 1) {
        int x = (t < 128 && t >= d) ? p[t - d] : 0;
        __syncthreads();
        if (t < 128) p[t] += x;
        __syncthreads();
    }
    int i = blockIdx.x * 256 + t;
    if (i < N_NODES) {
        int s = i >> 9;
        int base = (s == 0) ? 0 : p[s - 1];
        int o = g_off[i] + base;
        g_off[i] = o;
        g_cur[i] = o;
    }
    if (blockIdx.x == 0 && t == 0) g_off[N_NODES] = p[NB_SCAN - 1];
}

// ---------------- tf32 tensor-core GEMM tile, fp16 output --------------------
// C[M,N](half) = A[M,K](f32) @ W[K,N](f32). BM=128, BK=32 (round-6 geometry).
// 256 thr = 8 warps as 4(m) x 2(n); warp tile 32 x (N/2). NT = N/16.
// As[32][136] (bank stride 8), Bs[N][36] (bank stride 4): conflict-free frags.
template <int K, int N, int NT>
__device__ __forceinline__
void gemm_tf32(const float* __restrict__ A, const float* __restrict__ W,
               __half* __restrict__ C, int M, int m0) {
    __shared__ unsigned As[32][136];
    __shared__ unsigned Bs[N][36];

    const int t = threadIdx.x;
    const int lane = t & 31;
    const int wid = t >> 5;
    const int warp_m = wid >> 1;        // 0..3
    const int warp_n = wid & 1;         // 0..1
    const int lq = lane >> 2;           // 0..7
    const int lr = lane & 3;            // 0..3

    float acc[2][NT][4];
#pragma unroll
    for (int i = 0; i < 2; i++)
#pragma unroll
        for (int j = 0; j < NT; j++)
#pragma unroll
            for (int q = 0; q < 4; q++) acc[i][j][q] = 0.f;

    const int arow = t >> 1;            // 0..127 (staging row)
    const int aq0 = (t & 1) * 4;        // float4 quad base

    for (int kk = 0; kk < K; kk += 32) {
        // stage A tile [128 x 32] -> As[k][m], tf32
#pragma unroll
        for (int q = 0; q < 4; q++) {
            int kq = (aq0 + q) * 4;
            float4 v = make_float4(0.f, 0.f, 0.f, 0.f);
            if (m0 + arow < M)
                v = *reinterpret_cast<const float4*>(A + (size_t)(m0 + arow) * K + kk + kq);
            As[kq + 0][arow] = f2tf32(v.x);
            As[kq + 1][arow] = f2tf32(v.y);
            As[kq + 2][arow] = f2tf32(v.z);
            As[kq + 3][arow] = f2tf32(v.w);
        }
        // stage W tile [32 x N] -> Bs[n][k], tf32
        for (int i = t; i < 32 * N; i += 256) {
            int k = i / N;
            int n = i - k * N;
            Bs[n][k] = f2tf32(W[(size_t)(kk + k) * N + n]);
        }
        __syncthreads();

#pragma unroll
        for (int ks = 0; ks < 4; ks++) {
            const int k8 = ks * 8;
            unsigned b[NT][2];
            const int bn = warp_n * (NT * 8) + lq;
#pragma unroll
            for (int j = 0; j < NT; j++) {
                b[j][0] = Bs[bn + j * 8][k8 + lr];
                b[j][1] = Bs[bn + j * 8][k8 + lr + 4];
            }
            unsigned a[2][4];
            const int am = warp_m * 32 + lq;
#pragma unroll
            for (int i = 0; i < 2; i++) {
                int r = am + i * 16;
                a[i][0] = As[k8 + lr][r];
                a[i][1] = As[k8 + lr][r + 8];
                a[i][2] = As[k8 + lr + 4][r];
                a[i][3] = As[k8 + lr + 4][r + 8];
            }
#pragma unroll
            for (int i = 0; i < 2; i++)
#pragma unroll
                for (int j = 0; j < NT; j++) mma_tf32(acc[i][j], a[i], b[j]);
        }
        __syncthreads();
    }

    // epilogue -> fp16: c0,c1 at (r, 2lr),(r, 2lr+1); c2,c3 at (r+8, ...)
#pragma unroll
    for (int i = 0; i < 2; i++) {
        int r0 = m0 + warp_m * 32 + i * 16 + lq;
#pragma unroll
        for (int j = 0; j < NT; j++) {
            int c0 = warp_n * (NT * 8) + j * 8 + 2 * lr;
            if (r0 < M)
                *reinterpret_cast<__half2*>(C + (size_t)r0 * N + c0) =
                    __floats2half2_rn(acc[i][j][0], acc[i][j][1]);
            if (r0 + 8 < M)
                *reinterpret_cast<__half2*>(C + (size_t)(r0 + 8) * N + c0) =
                    __floats2half2_rn(acc[i][j][2], acc[i][j][3]);
        }
    }
}

// ---------------- K4: fat kernel — gemm1(tf32) || scatter || zero g_cnt ------
__global__ __launch_bounds__(256)
void fat1_kernel(const float* __restrict__ x, const float* __restrict__ W1,
                 const int* __restrict__ row, const int* __restrict__ col,
                 const float* __restrict__ ew, int E, int GB, int SCB) {
    int bid = blockIdx.x;
    int t = threadIdx.x;

    if (bid < GB) {
        gemm_tf32<NFEAT, NHID, 6>(x, W1, g_support1h, N_NODES, bid * 128);
    } else if (bid < GB + SCB) {
        int base = ((bid - GB) * 256 + t) * 4;
#pragma unroll
        for (int u = 0; u < 4; u++) {
            int e = base + u;
            if (e < E) {
                int p = atomicAdd(&g_cur[row[e]], 1);
                int2 packed;
                packed.x = col[e];
                packed.y = __float_as_int(ew[e]);
                g_es[p] = packed;
            }
        }
    } else {
        int base = ((bid - GB - SCB) * 256 + t) * 4;
#pragma unroll
        for (int u = 0; u < 4; u++) {
            int i = base + u;
            if (i < N_NODES) g_cnt[i] = 0;
        }
    }
}

// ---------------- K5: CSR SpMM layer 1 (fp16 gather) + bias + SELU -----------
// CH = 24 chunks of 4 halves per node; 24 threads per node.
__global__ __launch_bounds__(192)
void spmm1_kernel(const float* __restrict__ b1) {
    constexpr int CH = NHID / 4;
    int idx = blockIdx.x * 192 + threadIdx.x;
    int n = idx / CH;
    int c = idx - n * CH;
    if (n >= N_NODES) return;
    int off = g_off[n];
    int deg = g_off[n + 1] - off;
    const uint2* sup = reinterpret_cast<const uint2*>(g_support1h);

    float4 acc = make_float4(0.f, 0.f, 0.f, 0.f);
    int j = 0;
    for (; j + 3 < deg; j += 4) {
        int2 e0 = g_es[off + j];
        int2 e1 = g_es[off + j + 1];
        int2 e2 = g_es[off + j + 2];
        int2 e3 = g_es[off + j + 3];
        uint2 u0 = sup[(size_t)e0.x * CH + c];
        uint2 u1 = sup[(size_t)e1.x * CH + c];
        uint2 u2 = sup[(size_t)e2.x * CH + c];
        uint2 u3 = sup[(size_t)e3.x * CH + c];
        float w0 = __int_as_float(e0.y), w1 = __int_as_float(e1.y);
        float w2 = __int_as_float(e2.y), w3 = __int_as_float(e3.y);
        float2 a0 = __half22float2(*reinterpret_cast<__half2*>(&u0.x));
        float2 b0 = __half22float2(*reinterpret_cast<__half2*>(&u0.y));
        float2 a1 = __half22float2(*reinterpret_cast<__half2*>(&u1.x));
        float2 b1v = __half22float2(*reinterpret_cast<__half2*>(&u1.y));
        float2 a2 = __half22float2(*reinterpret_cast<__half2*>(&u2.x));
        float2 b2v = __half22float2(*reinterpret_cast<__half2*>(&u2.y));
        float2 a3 = __half22float2(*reinterpret_cast<__half2*>(&u3.x));
        float2 b3v = __half22float2(*reinterpret_cast<__half2*>(&u3.y));
        acc.x += w0 * a0.x + w1 * a1.x + w2 * a2.x + w3 * a3.x;
        acc.y += w0 * a0.y + w1 * a1.y + w2 * a2.y + w3 * a3.y;
        acc.z += w0 * b0.x + w1 * b1v.x + w2 * b2v.x + w3 * b3v.x;
        acc.w += w0 * b0.y + w1 * b1v.y + w2 * b2v.y + w3 * b3v.y;
    }
    for (; j < deg; j++) {
        int2 e0 = g_es[off + j];
        float w0 = __int_as_float(e0.y);
        uint2 u0 = sup[(size_t)e0.x * CH + c];
        float2 a0 = __half22float2(*reinterpret_cast<__half2*>(&u0.x));
        float2 b0 = __half22float2(*reinterpret_cast<__half2*>(&u0.y));
        acc.x += w0 * a0.x;
        acc.y += w0 * a0.y;
        acc.z += w0 * b0.x;
        acc.w += w0 * b0.y;
    }
    float4 bb = reinterpret_cast<const float4*>(b1)[c];
    float4 r;
    r.x = selu_f(acc.x + bb.x);
    r.y = selu_f(acc.y + bb.y);
    r.z = selu_f(acc.z + bb.z);
    r.w = selu_f(acc.w + bb.w);
    reinterpret_cast<float4*>(g_h1)[(size_t)n * CH + c] = r;
}

// ---------------- K6: GEMM layer 2 (tf32, fp16 out) --------------------------
__global__ __launch_bounds__(256)
void gemm2_kernel(const float* __restrict__ W2) {
    gemm_tf32<NHID, NCLASS, 4>(g_h1, W2, g_support2h, N_NODES, blockIdx.x * 128);
}

// ---------------- K7: SpMM layer 2 (fp16) + selu + pool + tail-block head ----
__global__ __launch_bounds__(256)
void spmm2_final_kernel(const float* __restrict__ b2,
                        const float* __restrict__ sub, const float* __restrict__ Wf,
                        const float* __restrict__ bf, const float* __restrict__ gamma,
                        const float* __restrict__ beta, const float* __restrict__ mean,
                        const float* __restrict__ var, float* __restrict__ out) {
    constexpr int CH = NCLASS / 4;
    __shared__ float sp[NCLASS];
    __shared__ int s_last;
    int t = threadIdx.x;
    if (t < NCLASS) sp[t] = 0.f;
    __syncthreads();

    int idx = blockIdx.x * 256 + t;
    int n = idx / CH;
    int c = idx - n * CH;
    float4 r = make_float4(0.f, 0.f, 0.f, 0.f);

    if (n < N_NODES) {
        int off = g_off[n];
        int deg = g_off[n + 1] - off;
        const uint2* sup = reinterpret_cast<const uint2*>(g_support2h);
        float4 acc = make_float4(0.f, 0.f, 0.f, 0.f);
        int j = 0;
        for (; j + 3 < deg; j += 4) {
            int2 e0 = g_es[off + j];
            int2 e1 = g_es[off + j + 1];
            int2 e2 = g_es[off + j + 2];
            int2 e3 = g_es[off + j + 3];
            uint2 u0 = sup[(size_t)e0.x * CH + c];
            uint2 u1 = sup[(size_t)e1.x * CH + c];
            uint2 u2 = sup[(size_t)e2.x * CH + c];
            uint2 u3 = sup[(size_t)e3.x * CH + c];
            float w0 = __int_as_float(e0.y), w1 = __int_as_float(e1.y);
            float w2 = __int_as_float(e2.y), w3 = __int_as_float(e3.y);
            float2 a0 = __half22float2(*reinterpret_cast<__half2*>(&u0.x));
            float2 b0 = __half22float2(*reinterpret_cast<__half2*>(&u0.y));
            float2 a1 = __half22float2(*reinterpret_cast<__half2*>(&u1.x));
            float2 b1v = __half22float2(*reinterpret_cast<__half2*>(&u1.y));
            float2 a2 = __half22float2(*reinterpret_cast<__half2*>(&u2.x));
            float2 b2v = __half22float2(*reinterpret_cast<__half2*>(&u2.y));
            float2 a3 = __half22float2(*reinterpret_cast<__half2*>(&u3.x));
            float2 b3v = __half22float2(*reinterpret_cast<__half2*>(&u3.y));
            acc.x += w0 * a0.x + w1 * a1.x + w2 * a2.x + w3 * a3.x;
            acc.y += w0 * a0.y + w1 * a1.y + w2 * a2.y + w3 * a3.y;
            acc.z += w0 * b0.x + w1 * b1v.x + w2 * b2v.x + w3 * b3v.x;
            acc.w += w0 * b0.y + w1 * b1v.y + w2 * b2v.y + w3 * b3v.y;
        }
        for (; j < deg; j++) {
            int2 e0 = g_es[off + j];
            float w0 = __int_as_float(e0.y);
            uint2 u0 = sup[(size_t)e0.x * CH + c];
            float2 a0 = __half22float2(*reinterpret_cast<__half2*>(&u0.x));
            float2 b0 = __half22float2(*reinterpret_cast<__half2*>(&u0.y));
            acc.x += w0 * a0.x;
            acc.y += w0 * a0.y;
            acc.z += w0 * b0.x;
            acc.w += w0 * b0.y;
        }
        float4 bb = reinterpret_cast<const float4*>(b2)[c];
        r.x = selu_f(acc.x + bb.x);
        r.y = selu_f(acc.y + bb.y);
        r.z = selu_f(acc.z + bb.z);
        r.w = selu_f(acc.w + bb.w);
    }

    r.x += __shfl_xor_sync(0xffffffffu, r.x, 16);
    r.y += __shfl_xor_sync(0xffffffffu, r.y, 16);
    r.z += __shfl_xor_sync(0xffffffffu, r.z, 16);
    r.w += __shfl_xor_sync(0xffffffffu, r.w, 16);
    if ((t & 16) == 0) {
        atomicAdd(&sp[c * 4 + 0], r.x);
        atomicAdd(&sp[c * 4 + 1], r.y);
        atomicAdd(&sp[c * 4 + 2], r.z);
        atomicAdd(&sp[c * 4 + 3], r.w);
    }
    __syncthreads();
    if (t < NCLASS) atomicAdd(&g_pool[t], sp[t]);

    __threadfence();
    __syncthreads();
    if (t == 0) s_last = (atomicAdd(&g_done, 1) == (int)gridDim.x - 1);
    __syncthreads();
    if (!s_last) return;
    __threadfence();

    __shared__ float z[NCLASS + NEXT];
    __shared__ float logits[NCLASS];
    __shared__ float red[256];
    __shared__ float s_max, s_lse;

    if (t < NCLASS) {
        z[t] = selu_f(__ldcg(&g_pool[t]) / (float)N_NODES);
    } else if (t < NCLASS + NEXT) {
        int jj = t - NCLASS;
        z[t] = (sub[jj] - mean[jj]) * rsqrtf(var[jj] + BN_EPS) * gamma[jj] + beta[jj];
    }
    __syncthreads();

    if (t < NCLASS) {
        float a = bf[t];
        const float* wrow = Wf + (size_t)t * (NCLASS + NEXT);
#pragma unroll
        for (int k = 0; k < NCLASS + NEXT; k++) a += z[k] * wrow[k];
        logits[t] = a;
    }
    __syncthreads();

    if (t == 0) {
        float m = -INFINITY;
        for (int k = 0; k < NCLASS; k++) m = fmaxf(m, logits[k]);
        float s = 0.f;
        for (int k = 0; k < NCLASS; k++) s += expf(logits[k] - m);
        s_max = m;
        s_lse = logf(s);
    }
    __syncthreads();
    if (t < NCLASS) out[t] = logits[t] - s_max - s_lse;

    float l = 0.f;
    const int TOTW = NCLASS * (NCLASS + NEXT);
    for (int i = t; i < TOTW; i += 256) l += fabsf(Wf[i]);
    red[t] = l;
    __syncthreads();
    for (int s2 = 128; s2 > 0; s2 >>= 1) {
        if (t < s2) red[t] += red[t + s2];
        __syncthreads();
    }
    if (t == 0) out[NCLASS] = red[0] / (float)TOTW;

    if (t < NCLASS) g_pool[t] = 0.f;
    if (t == 0) g_done = 0;
}

// ---------------- launch -----------------------------------------------------
extern "C" void kernel_launch(void* const* d_in, const int* in_sizes, int n_in,
                              void* d_out, int out_size) {
    const float* x     = (const float*)d_in[0];
    const int*   row   = (const int*)  d_in[1];
    const int*   col   = (const int*)  d_in[2];
    const float* ew    = (const float*)d_in[3];
    const float* sub   = (const float*)d_in[4];
    const float* W1    = (const float*)d_in[5];
    const float* b1    = (const float*)d_in[6];
    const float* W2    = (const float*)d_in[7];
    const float* b2    = (const float*)d_in[8];
    const float* Wf    = (const float*)d_in[9];
    const float* bf    = (const float*)d_in[10];
    const float* gamma = (const float*)d_in[11];
    const float* beta  = (const float*)d_in[12];
    const float* mean  = (const float*)d_in[13];
    const float* var   = (const float*)d_in[14];
    float* out = (float*)d_out;

    const int E = (n_in > 1) ? in_sizes[1] : N_EDGES;

    const int GB  = (N_NODES + 127) / 128;   // 391 gemm blocks (BM=128)
    const int SCB = (E + 1023) / 1024;       // scatter blocks
    const int ZB  = (N_NODES + 1023) / 1024; // zero blocks

    hist_kernel<<<(E + 255) / 256, 256>>>(row, E);
    scanA_kernel<<<NB_SCAN, SCAN_B>>>();
    scanBC_kernel<<<(N_NODES + 255) / 256, 256>>>();
    fat1_kernel<<<GB + SCB + ZB, 256>>>(x, W1, row, col, ew, E, GB, SCB);
    spmm1_kernel<<<(N_NODES * (NHID / 4) + 191) / 192, 192>>>(b1);
    gemm2_kernel<<<GB, 256>>>(W2);
    spmm2_final_kernel<<<(N_NODES * (NCLASS / 4) + 255) / 256, 256>>>(
        b2, sub, Wf, bf, gamma, beta, mean, var, out);
}

// round 10
// speedup vs baseline: 1.2143x; 1.0770x over previous
#include <cuda_runtime.h>
#include <cuda_fp16.h>
#include <math.h>

#define N_NODES 50000
#define N_EDGES 800000
#define NFEAT 128
#define NHID 96
#define NCLASS 64
#define NEXT 32
#define BN_EPS 1e-5f

// ---------------- scratch (device globals; zero-initialized at load) --------
// Invariant at entry/exit: g_cnt == 0, g_pool == 0, g_done == 0, g_total == 0.
__device__ __align__(16) __half g_support1h[N_NODES * NHID];   // x@W1 (fp16)
__device__ __align__(16) float  g_h1[N_NODES * NHID];          // selu(agg1+b1)
__device__ __align__(16) __half g_support2h[N_NODES * NCLASS]; // h1@W2 (fp16)
__device__ float g_pool[NCLASS];
__device__ int   g_done;
__device__ int   g_total;

__device__ int  g_cnt[N_NODES];
__device__ int2 g_od[N_NODES];                 // (offset, degree) per node
__device__ int  g_cur[N_NODES];
__device__ int2 g_es[N_EDGES];                 // packed (col, w) grouped by row

// ---------------- helpers ----------------------------------------------------
__device__ __forceinline__ float selu_f(float v) {
    const float scale = 1.0507009873554805f;
    const float alpha = 1.6732632423543772f;
    return scale * (v > 0.0f ? v : alpha * (expf(v) - 1.0f));
}

__device__ __forceinline__ void ldsm_x4(unsigned addr, unsigned& r0, unsigned& r1,
                                        unsigned& r2, unsigned& r3) {
    asm volatile("ldmatrix.sync.aligned.m8n8.x4.shared.b16 {%0,%1,%2,%3}, [%4];"
                 : "=r"(r0), "=r"(r1), "=r"(r2), "=r"(r3) : "r"(addr));
}

__device__ __forceinline__ void ldsm_x2(unsigned addr, unsigned& r0, unsigned& r1) {
    asm volatile("ldmatrix.sync.aligned.m8n8.x2.shared.b16 {%0,%1}, [%2];"
                 : "=r"(r0), "=r"(r1) : "r"(addr));
}

__device__ __forceinline__ void mma_f16(float c[4], const unsigned a[4],
                                        const unsigned b[2]) {
    asm volatile(
        "mma.sync.aligned.m16n8k16.row.col.f32.f16.f16.f32 "
        "{%0,%1,%2,%3}, {%4,%5,%6,%7}, {%8,%9}, {%0,%1,%2,%3};"
        : "+f"(c[0]), "+f"(c[1]), "+f"(c[2]), "+f"(c[3])
        : "r"(a[0]), "r"(a[1]), "r"(a[2]), "r"(a[3]), "r"(b[0]), "r"(b[1]));
}

__device__ __forceinline__ unsigned h2u(__half2 h) {
    return *reinterpret_cast<unsigned*>(&h);
}

// ---------------- K1: histogram ----------------------------------------------
__global__ void hist_kernel(const int* __restrict__ row, int E) {
    int e = blockIdx.x * blockDim.x + threadIdx.x;
    if (e < E) atomicAdd(&g_cnt[row[e]], 1);
}

// ---------------- K2: unordered CSR allocation (replaces both scans) ---------
// Offsets need not be monotonic, only per-node contiguous. Warp-aggregated
// atomic allocation + inline zeroing of g_cnt (restores invariant).
__global__ __launch_bounds__(256)
void alloc_kernel() {
    int i = blockIdx.x * 256 + threadIdx.x;
    int lane = threadIdx.x & 31;
    int cnt = (i < N_NODES) ? g_cnt[i] : 0;
    int incl = cnt;
#pragma unroll
    for (int d = 1; d < 32; d <<= 1) {
        int v = __shfl_up_sync(0xffffffffu, incl, d);
        if (lane >= d) incl += v;
    }
    int total = __shfl_sync(0xffffffffu, incl, 31);
    int base = 0;
    if (lane == 0) base = atomicAdd(&g_total, total);
    base = __shfl_sync(0xffffffffu, base, 0);
    if (i < N_NODES) {
        int off = base + incl - cnt;
        g_od[i] = make_int2(off, cnt);
        g_cur[i] = off;
        g_cnt[i] = 0;
    }
}

// ---------------- fp16 tensor-core GEMM tile (ldmatrix + m16n8k16) -----------
// C[M,N](half) = A[M,K](f32) @ W[K,N](f32). BM=128, BK=32.
// 256 thr = 8 warps as 4(m) x 2(n); warp tile 32 x (NT*8), NT = N/16.
// SMEM rows stride 40 halves = 80 B: multiple of 16 (ldmatrix row-alignment
// requirement) and 20-word stride -> 8-row ldmatrix sets hit distinct banks
// ({0,20,8,28,16,4,24,12}).
template <int K, int N, int NT>
__device__ __forceinline__
void gemm_f16(const float* __restrict__ A, const float* __restrict__ W,
              __half* __restrict__ C, int M, int m0) {
    __shared__ __align__(16) __half As[128][40];
    __shared__ __align__(16) __half Bs[N][40];

    const int t = threadIdx.x;
    const int lane = t & 31;
    const int wid = t >> 5;
    const int warp_m = wid >> 1;        // 0..3
    const int warp_n = wid & 1;         // 0..1
    const int lq = lane >> 2;           // 0..7
    const int lr = lane & 3;            // 0..3

    const unsigned as_base = (unsigned)__cvta_generic_to_shared(&As[0][0]);
    const unsigned bs_base = (unsigned)__cvta_generic_to_shared(&Bs[0][0]);

    float acc[2][NT][4];
#pragma unroll
    for (int i = 0; i < 2; i++)
#pragma unroll
        for (int j = 0; j < NT; j++)
#pragma unroll
            for (int q = 0; q < 4; q++) acc[i][j][q] = 0.f;

    const int arow = t >> 1;            // 0..127 staging row
    const int ah = (t & 1) * 16;        // halves base within BK=32

    for (int kk = 0; kk < K; kk += 32) {
        // stage A tile [128 x 32] fp32 -> fp16
#pragma unroll
        for (int q = 0; q < 4; q++) {
            int kq = ah + q * 4;
            float4 v = make_float4(0.f, 0.f, 0.f, 0.f);
            if (m0 + arow < M)
                v = *reinterpret_cast<const float4*>(A + (size_t)(m0 + arow) * K + kk + kq);
            uint2 u;
            u.x = h2u(__floats2half2_rn(v.x, v.y));
            u.y = h2u(__floats2half2_rn(v.z, v.w));
            *reinterpret_cast<uint2*>(
                reinterpret_cast<char*>(&As[0][0]) + arow * 80 + kq * 2) = u;
        }
        // stage W tile [32 x N] fp32 -> Bs[n][k] fp16
#pragma unroll
        for (int r = 0; r < (32 * N) / 256; r++) {
            int i = t + r * 256;
            int k = i / N;
            int n = i - k * N;
            Bs[n][k] = __float2half_rn(W[(size_t)(kk + k) * N + n]);
        }
        __syncthreads();

#pragma unroll
        for (int ks = 0; ks < 2; ks++) {
            const int k16 = ks * 16;
            // B fragments: NT tiles of n8, each one ldmatrix.x2
            unsigned b[NT][2];
            const int bl = lane & 15;
            const int brow = bl & 7;
            const int bk = k16 + ((bl >> 3) & 1) * 8;
#pragma unroll
            for (int j = 0; j < NT; j++) {
                unsigned addr = bs_base +
                    (unsigned)((warp_n * (NT * 8) + j * 8 + brow) * 80 + bk * 2);
                ldsm_x2(addr, b[j][0], b[j][1]);
            }
            // A fragments + MMAs
            const int g = lane >> 3;
            const int rowl = lane & 7;
            const int ar_add = (g & 1) * 8 + rowl;
            const int ak = k16 + (g >> 1) * 8;
#pragma unroll
            for (int i = 0; i < 2; i++) {
                unsigned a[4];
                unsigned addr = as_base +
                    (unsigned)((warp_m * 32 + i * 16 + ar_add) * 80 + ak * 2);
                ldsm_x4(addr, a[0], a[1], a[2], a[3]);
#pragma unroll
                for (int j = 0; j < NT; j++) mma_f16(acc[i][j], a, b[j]);
            }
        }
        __syncthreads();
    }

    // epilogue -> fp16: c0,c1 at (r, 2lr),(r, 2lr+1); c2,c3 at (r+8, ...)
#pragma unroll
    for (int i = 0; i < 2; i++) {
        int r0 = m0 + warp_m * 32 + i * 16 + lq;
#pragma unroll
        for (int j = 0; j < NT; j++) {
            int c0 = warp_n * (NT * 8) + j * 8 + 2 * lr;
            if (r0 < M)
                *reinterpret_cast<__half2*>(C + (size_t)r0 * N + c0) =
                    __floats2half2_rn(acc[i][j][0], acc[i][j][1]);
            if (r0 + 8 < M)
                *reinterpret_cast<__half2*>(C + (size_t)(r0 + 8) * N + c0) =
                    __floats2half2_rn(acc[i][j][2], acc[i][j][3]);
        }
    }
}

// ---------------- K3: fat kernel — gemm1(fp16 mma) || scatter ----------------
__global__ __launch_bounds__(256)
void fat1_kernel(const float* __restrict__ x, const float* __restrict__ W1,
                 const int* __restrict__ row, const int* __restrict__ col,
                 const float* __restrict__ ew, int E, int GB) {
    int bid = blockIdx.x;
    int t = threadIdx.x;

    if (bid < GB) {
        gemm_f16<NFEAT, NHID, 6>(x, W1, g_support1h, N_NODES, bid * 128);
    } else {
        int base = ((bid - GB) * 256 + t) * 4;
#pragma unroll
        for (int u = 0; u < 4; u++) {
            int e = base + u;
            if (e < E) {
                int p = atomicAdd(&g_cur[row[e]], 1);
                int2 packed;
                packed.x = col[e];
                packed.y = __float_as_int(ew[e]);
                g_es[p] = packed;
            }
        }
    }
}

// ---------------- K4: CSR SpMM layer 1 (fp16 gather) + bias + SELU -----------
__global__ __launch_bounds__(192)
void spmm1_kernel(const float* __restrict__ b1) {
    constexpr int CH = NHID / 4;
    int idx = blockIdx.x * 192 + threadIdx.x;
    int n = idx / CH;
    int c = idx - n * CH;
    if (n >= N_NODES) return;
    int2 od = g_od[n];
    int off = od.x;
    int deg = od.y;
    const uint2* sup = reinterpret_cast<const uint2*>(g_support1h);

    float4 acc = make_float4(0.f, 0.f, 0.f, 0.f);
    int j = 0;
    for (; j + 3 < deg; j += 4) {
        int2 e0 = g_es[off + j];
        int2 e1 = g_es[off + j + 1];
        int2 e2 = g_es[off + j + 2];
        int2 e3 = g_es[off + j + 3];
        uint2 u0 = sup[(size_t)e0.x * CH + c];
        uint2 u1 = sup[(size_t)e1.x * CH + c];
        uint2 u2 = sup[(size_t)e2.x * CH + c];
        uint2 u3 = sup[(size_t)e3.x * CH + c];
        float w0 = __int_as_float(e0.y), w1 = __int_as_float(e1.y);
        float w2 = __int_as_float(e2.y), w3 = __int_as_float(e3.y);
        float2 a0 = __half22float2(*reinterpret_cast<__half2*>(&u0.x));
        float2 b0 = __half22float2(*reinterpret_cast<__half2*>(&u0.y));
        float2 a1 = __half22float2(*reinterpret_cast<__half2*>(&u1.x));
        float2 b1v = __half22float2(*reinterpret_cast<__half2*>(&u1.y));
        float2 a2 = __half22float2(*reinterpret_cast<__half2*>(&u2.x));
        float2 b2v = __half22float2(*reinterpret_cast<__half2*>(&u2.y));
        float2 a3 = __half22float2(*reinterpret_cast<__half2*>(&u3.x));
        float2 b3v = __half22float2(*reinterpret_cast<__half2*>(&u3.y));
        acc.x += w0 * a0.x + w1 * a1.x + w2 * a2.x + w3 * a3.x;
        acc.y += w0 * a0.y + w1 * a1.y + w2 * a2.y + w3 * a3.y;
        acc.z += w0 * b0.x + w1 * b1v.x + w2 * b2v.x + w3 * b3v.x;
        acc.w += w0 * b0.y + w1 * b1v.y + w2 * b2v.y + w3 * b3v.y;
    }
    for (; j < deg; j++) {
        int2 e0 = g_es[off + j];
        float w0 = __int_as_float(e0.y);
        uint2 u0 = sup[(size_t)e0.x * CH + c];
        float2 a0 = __half22float2(*reinterpret_cast<__half2*>(&u0.x));
        float2 b0 = __half22float2(*reinterpret_cast<__half2*>(&u0.y));
        acc.x += w0 * a0.x;
        acc.y += w0 * a0.y;
        acc.z += w0 * b0.x;
        acc.w += w0 * b0.y;
    }
    float4 bb = reinterpret_cast<const float4*>(b1)[c];
    float4 r;
    r.x = selu_f(acc.x + bb.x);
    r.y = selu_f(acc.y + bb.y);
    r.z = selu_f(acc.z + bb.z);
    r.w = selu_f(acc.w + bb.w);
    reinterpret_cast<float4*>(g_h1)[(size_t)n * CH + c] = r;
}

// ---------------- K5: GEMM layer 2 (fp16 mma) --------------------------------
__global__ __launch_bounds__(256)
void gemm2_kernel(const float* __restrict__ W2) {
    gemm_f16<NHID, NCLASS, 4>(g_h1, W2, g_support2h, N_NODES, blockIdx.x * 128);
}

// ---------------- K6: SpMM layer 2 (fp16) + selu + pool + tail-block head ----
__global__ __launch_bounds__(256)
void spmm2_final_kernel(const float* __restrict__ b2,
                        const float* __restrict__ sub, const float* __restrict__ Wf,
                        const float* __restrict__ bf, const float* __restrict__ gamma,
                        const float* __restrict__ beta, const float* __restrict__ mean,
                        const float* __restrict__ var, float* __restrict__ out) {
    constexpr int CH = NCLASS / 4;
    __shared__ float sp[NCLASS];
    __shared__ int s_last;
    int t = threadIdx.x;
    if (t < NCLASS) sp[t] = 0.f;
    __syncthreads();

    int idx = blockIdx.x * 256 + t;
    int n = idx / CH;
    int c = idx - n * CH;
    float4 r = make_float4(0.f, 0.f, 0.f, 0.f);

    if (n < N_NODES) {
        int2 od = g_od[n];
        int off = od.x;
        int deg = od.y;
        const uint2* sup = reinterpret_cast<const uint2*>(g_support2h);
        float4 acc = make_float4(0.f, 0.f, 0.f, 0.f);
        int j = 0;
        for (; j + 3 < deg; j += 4) {
            int2 e0 = g_es[off + j];
            int2 e1 = g_es[off + j + 1];
            int2 e2 = g_es[off + j + 2];
            int2 e3 = g_es[off + j + 3];
            uint2 u0 = sup[(size_t)e0.x * CH + c];
            uint2 u1 = sup[(size_t)e1.x * CH + c];
            uint2 u2 = sup[(size_t)e2.x * CH + c];
            uint2 u3 = sup[(size_t)e3.x * CH + c];
            float w0 = __int_as_float(e0.y), w1 = __int_as_float(e1.y);
            float w2 = __int_as_float(e2.y), w3 = __int_as_float(e3.y);
            float2 a0 = __half22float2(*reinterpret_cast<__half2*>(&u0.x));
            float2 b0 = __half22float2(*reinterpret_cast<__half2*>(&u0.y));
            float2 a1 = __half22float2(*reinterpret_cast<__half2*>(&u1.x));
            float2 b1v = __half22float2(*reinterpret_cast<__half2*>(&u1.y));
            float2 a2 = __half22float2(*reinterpret_cast<__half2*>(&u2.x));
            float2 b2v = __half22float2(*reinterpret_cast<__half2*>(&u2.y));
            float2 a3 = __half22float2(*reinterpret_cast<__half2*>(&u3.x));
            float2 b3v = __half22float2(*reinterpret_cast<__half2*>(&u3.y));
            acc.x += w0 * a0.x + w1 * a1.x + w2 * a2.x + w3 * a3.x;
            acc.y += w0 * a0.y + w1 * a1.y + w2 * a2.y + w3 * a3.y;
            acc.z += w0 * b0.x + w1 * b1v.x + w2 * b2v.x + w3 * b3v.x;
            acc.w += w0 * b0.y + w1 * b1v.y + w2 * b2v.y + w3 * b3v.y;
        }
        for (; j < deg; j++) {
            int2 e0 = g_es[off + j];
            float w0 = __int_as_float(e0.y);
            uint2 u0 = sup[(size_t)e0.x * CH + c];
            float2 a0 = __half22float2(*reinterpret_cast<__half2*>(&u0.x));
            float2 b0 = __half22float2(*reinterpret_cast<__half2*>(&u0.y));
            acc.x += w0 * a0.x;
            acc.y += w0 * a0.y;
            acc.z += w0 * b0.x;
            acc.w += w0 * b0.y;
        }
        float4 bb = reinterpret_cast<const float4*>(b2)[c];
        r.x = selu_f(acc.x + bb.x);
        r.y = selu_f(acc.y + bb.y);
        r.z = selu_f(acc.z + bb.z);
        r.w = selu_f(acc.w + bb.w);
    }

    r.x += __shfl_xor_sync(0xffffffffu, r.x, 16);
    r.y += __shfl_xor_sync(0xffffffffu, r.y, 16);
    r.z += __shfl_xor_sync(0xffffffffu, r.z, 16);
    r.w += __shfl_xor_sync(0xffffffffu, r.w, 16);
    if ((t & 16) == 0) {
        atomicAdd(&sp[c * 4 + 0], r.x);
        atomicAdd(&sp[c * 4 + 1], r.y);
        atomicAdd(&sp[c * 4 + 2], r.z);
        atomicAdd(&sp[c * 4 + 3], r.w);
    }
    __syncthreads();
    if (t < NCLASS) atomicAdd(&g_pool[t], sp[t]);

    __threadfence();
    __syncthreads();
    if (t == 0) s_last = (atomicAdd(&g_done, 1) == (int)gridDim.x - 1);
    __syncthreads();
    if (!s_last) return;
    __threadfence();

    __shared__ float z[NCLASS + NEXT];
    __shared__ float logits[NCLASS];
    __shared__ float red[256];
    __shared__ float s_max, s_lse;

    if (t < NCLASS) {
        z[t] = selu_f(__ldcg(&g_pool[t]) / (float)N_NODES);
    } else if (t < NCLASS + NEXT) {
        int jj = t - NCLASS;
        z[t] = (sub[jj] - mean[jj]) * rsqrtf(var[jj] + BN_EPS) * gamma[jj] + beta[jj];
    }
    __syncthreads();

    if (t < NCLASS) {
        float a = bf[t];
        const float* wrow = Wf + (size_t)t * (NCLASS + NEXT);
#pragma unroll
        for (int k = 0; k < NCLASS + NEXT; k++) a += z[k] * wrow[k];
        logits[t] = a;
    }
    __syncthreads();

    if (t == 0) {
        float m = -INFINITY;
        for (int k = 0; k < NCLASS; k++) m = fmaxf(m, logits[k]);
        float s = 0.f;
        for (int k = 0; k < NCLASS; k++) s += expf(logits[k] - m);
        s_max = m;
        s_lse = logf(s);
    }
    __syncthreads();
    if (t < NCLASS) out[t] = logits[t] - s_max - s_lse;

    float l = 0.f;
    const int TOTW = NCLASS * (NCLASS + NEXT);
    for (int i = t; i < TOTW; i += 256) l += fabsf(Wf[i]);
    red[t] = l;
    __syncthreads();
    for (int s2 = 128; s2 > 0; s2 >>= 1) {
        if (t < s2) red[t] += red[t + s2];
        __syncthreads();
    }
    if (t == 0) out[NCLASS] = red[0] / (float)TOTW;

    // restore invariants
    if (t < NCLASS) g_pool[t] = 0.f;
    if (t == 0) { g_done = 0; g_total = 0; }
}

// ---------------- launch -----------------------------------------------------
extern "C" void kernel_launch(void* const* d_in, const int* in_sizes, int n_in,
                              void* d_out, int out_size) {
    const float* x     = (const float*)d_in[0];
    const int*   row   = (const int*)  d_in[1];
    const int*   col   = (const int*)  d_in[2];
    const float* ew    = (const float*)d_in[3];
    const float* sub   = (const float*)d_in[4];
    const float* W1    = (const float*)d_in[5];
    const float* b1    = (const float*)d_in[6];
    const float* W2    = (const float*)d_in[7];
    const float* b2    = (const float*)d_in[8];
    const float* Wf    = (const float*)d_in[9];
    const float* bf    = (const float*)d_in[10];
    const float* gamma = (const float*)d_in[11];
    const float* beta  = (const float*)d_in[12];
    const float* mean  = (const float*)d_in[13];
    const float* var   = (const float*)d_in[14];
    float* out = (float*)d_out;

    const int E = (n_in > 1) ? in_sizes[1] : N_EDGES;

    const int GB  = (N_NODES + 127) / 128;   // 391 gemm blocks (BM=128)
    const int SCB = (E + 1023) / 1024;       // scatter blocks (4 edges/thread)

    hist_kernel<<<(E + 255) / 256, 256>>>(row, E);
    alloc_kernel<<<(N_NODES + 255) / 256, 256>>>();
    fat1_kernel<<<GB + SCB, 256>>>(x, W1, row, col, ew, E, GB);
    spmm1_kernel<<<(N_NODES * (NHID / 4) + 191) / 192, 192>>>(b1);
    gemm2_kernel<<<GB, 256>>>(W2);
    spmm2_final_kernel<<<(N_NODES * (NCLASS / 4) + 255) / 256, 256>>>(
        b2, sub, Wf, bf, gamma, beta, mean, var, out);
}

// round 12
// speedup vs baseline: 1.4034x; 1.1558x over previous
#include <cuda_runtime.h>
#include <cuda_fp16.h>
#include <math.h>

#define N_NODES 50000
#define N_EDGES 800000
#define NFEAT 128
#define NHID 96
#define NCLASS 64
#define NEXT 32
#define BN_EPS 1e-5f

// ---------------- scratch (device globals; zero-initialized at load) --------
// Invariant at entry/exit: g_cnt == 0, g_pool == 0, g_done == 0, g_total == 0.
__device__ __align__(16) __half g_support1h[N_NODES * NHID];   // x@W1 (fp16)
__device__ __align__(16) __half g_support2h[N_NODES * NCLASS]; // h2 pre-agg (fp16)
__device__ float g_pool[NCLASS];
__device__ int   g_done;
__device__ int   g_total;

__device__ int  g_cnt[N_NODES];
__device__ int2 g_od[N_NODES];                 // (offset, degree) per node
__device__ int  g_cur[N_NODES];
__device__ int2 g_es[N_EDGES];                 // packed (col, w) grouped by row

// ---------------- helpers ----------------------------------------------------
__device__ __forceinline__ float selu_f(float v) {
    const float scale = 1.0507009873554805f;
    const float alpha = 1.6732632423543772f;
    return scale * (v > 0.0f ? v : alpha * (expf(v) - 1.0f));
}

__device__ __forceinline__ void ldsm_x4(unsigned addr, unsigned& r0, unsigned& r1,
                                        unsigned& r2, unsigned& r3) {
    asm volatile("ldmatrix.sync.aligned.m8n8.x4.shared.b16 {%0,%1,%2,%3}, [%4];"
                 : "=r"(r0), "=r"(r1), "=r"(r2), "=r"(r3) : "r"(addr));
}

__device__ __forceinline__ void ldsm_x2(unsigned addr, unsigned& r0, unsigned& r1) {
    asm volatile("ldmatrix.sync.aligned.m8n8.x2.shared.b16 {%0,%1}, [%2];"
                 : "=r"(r0), "=r"(r1) : "r"(addr));
}

__device__ __forceinline__ void mma_f16(float c[4], const unsigned a[4],
                                        const unsigned b[2]) {
    asm volatile(
        "mma.sync.aligned.m16n8k16.row.col.f32.f16.f16.f32 "
        "{%0,%1,%2,%3}, {%4,%5,%6,%7}, {%8,%9}, {%0,%1,%2,%3};"
        : "+f"(c[0]), "+f"(c[1]), "+f"(c[2]), "+f"(c[3])
        : "r"(a[0]), "r"(a[1]), "r"(a[2]), "r"(a[3]), "r"(b[0]), "r"(b[1]));
}

__device__ __forceinline__ unsigned h2u(__half2 h) {
    return *reinterpret_cast<unsigned*>(&h);
}

// accumulate 8 halves (uint4) * w into acc[8]
__device__ __forceinline__ void acc8(float acc[8], uint4 u, float w) {
    float2 p0 = __half22float2(*reinterpret_cast<__half2*>(&u.x));
    float2 p1 = __half22float2(*reinterpret_cast<__half2*>(&u.y));
    float2 p2 = __half22float2(*reinterpret_cast<__half2*>(&u.z));
    float2 p3 = __half22float2(*reinterpret_cast<__half2*>(&u.w));
    acc[0] += w * p0.x; acc[1] += w * p0.y;
    acc[2] += w * p1.x; acc[3] += w * p1.y;
    acc[4] += w * p2.x; acc[5] += w * p2.y;
    acc[6] += w * p3.x; acc[7] += w * p3.y;
}

// ---------------- K1: histogram ----------------------------------------------
__global__ void hist_kernel(const int* __restrict__ row, int E) {
    int e = blockIdx.x * blockDim.x + threadIdx.x;
    if (e < E) atomicAdd(&g_cnt[row[e]], 1);
}

// ---------------- K2: unordered CSR allocation -------------------------------
__global__ __launch_bounds__(256)
void alloc_kernel() {
    int i = blockIdx.x * 256 + threadIdx.x;
    int lane = threadIdx.x & 31;
    int cnt = (i < N_NODES) ? g_cnt[i] : 0;
    int incl = cnt;
#pragma unroll
    for (int d = 1; d < 32; d <<= 1) {
        int v = __shfl_up_sync(0xffffffffu, incl, d);
        if (lane >= d) incl += v;
    }
    int total = __shfl_sync(0xffffffffu, incl, 31);
    int base = 0;
    if (lane == 0) base = atomicAdd(&g_total, total);
    base = __shfl_sync(0xffffffffu, base, 0);
    if (i < N_NODES) {
        int off = base + incl - cnt;
        g_od[i] = make_int2(off, cnt);
        g_cur[i] = off;
        g_cnt[i] = 0;
    }
}

// ---------------- fp16 tensor-core GEMM tile (for gemm1, stride 40) ----------
template <int K, int N, int NT>
__device__ __forceinline__
void gemm_f16(const float* __restrict__ A, const float* __restrict__ W,
              __half* __restrict__ C, int M, int m0) {
    __shared__ __align__(16) __half As[128][40];
    __shared__ __align__(16) __half Bs[N][40];

    const int t = threadIdx.x;
    const int lane = t & 31;
    const int wid = t >> 5;
    const int warp_m = wid >> 1;
    const int warp_n = wid & 1;
    const int lq = lane >> 2;
    const int lr = lane & 3;

    const unsigned as_base = (unsigned)__cvta_generic_to_shared(&As[0][0]);
    const unsigned bs_base = (unsigned)__cvta_generic_to_shared(&Bs[0][0]);

    float acc[2][NT][4];
#pragma unroll
    for (int i = 0; i < 2; i++)
#pragma unroll
        for (int j = 0; j < NT; j++)
#pragma unroll
            for (int q = 0; q < 4; q++) acc[i][j][q] = 0.f;

    const int arow = t >> 1;
    const int ah = (t & 1) * 16;

    for (int kk = 0; kk < K; kk += 32) {
#pragma unroll
        for (int q = 0; q < 4; q++) {
            int kq = ah + q * 4;
            float4 v = make_float4(0.f, 0.f, 0.f, 0.f);
            if (m0 + arow < M)
                v = *reinterpret_cast<const float4*>(A + (size_t)(m0 + arow) * K + kk + kq);
            uint2 u;
            u.x = h2u(__floats2half2_rn(v.x, v.y));
            u.y = h2u(__floats2half2_rn(v.z, v.w));
            *reinterpret_cast<uint2*>(
                reinterpret_cast<char*>(&As[0][0]) + arow * 80 + kq * 2) = u;
        }
#pragma unroll
        for (int r = 0; r < (32 * N) / 256; r++) {
            int i = t + r * 256;
            int k = i / N;
            int n = i - k * N;
            Bs[n][k] = __float2half_rn(W[(size_t)(kk + k) * N + n]);
        }
        __syncthreads();

#pragma unroll
        for (int ks = 0; ks < 2; ks++) {
            const int k16 = ks * 16;
            unsigned b[NT][2];
            const int bl = lane & 15;
            const int brow = bl & 7;
            const int bk = k16 + ((bl >> 3) & 1) * 8;
#pragma unroll
            for (int j = 0; j < NT; j++) {
                unsigned addr = bs_base +
                    (unsigned)((warp_n * (NT * 8) + j * 8 + brow) * 80 + bk * 2);
                ldsm_x2(addr, b[j][0], b[j][1]);
            }
            const int g = lane >> 3;
            const int rowl = lane & 7;
            const int ar_add = (g & 1) * 8 + rowl;
            const int ak = k16 + (g >> 1) * 8;
#pragma unroll
            for (int i = 0; i < 2; i++) {
                unsigned a[4];
                unsigned addr = as_base +
                    (unsigned)((warp_m * 32 + i * 16 + ar_add) * 80 + ak * 2);
                ldsm_x4(addr, a[0], a[1], a[2], a[3]);
#pragma unroll
                for (int j = 0; j < NT; j++) mma_f16(acc[i][j], a, b[j]);
            }
        }
        __syncthreads();
    }

#pragma unroll
    for (int i = 0; i < 2; i++) {
        int r0 = m0 + warp_m * 32 + i * 16 + lq;
#pragma unroll
        for (int j = 0; j < NT; j++) {
            int c0 = warp_n * (NT * 8) + j * 8 + 2 * lr;
            if (r0 < M)
                *reinterpret_cast<__half2*>(C + (size_t)r0 * N + c0) =
                    __floats2half2_rn(acc[i][j][0], acc[i][j][1]);
            if (r0 + 8 < M)
                *reinterpret_cast<__half2*>(C + (size_t)(r0 + 8) * N + c0) =
                    __floats2half2_rn(acc[i][j][2], acc[i][j][3]);
        }
    }
}

// ---------------- K3: fat kernel — gemm1(fp16 mma) || scatter ----------------
__global__ __launch_bounds__(256)
void fat1_kernel(const float* __restrict__ x, const float* __restrict__ W1,
                 const int* __restrict__ row, const int* __restrict__ col,
                 const float* __restrict__ ew, int E, int GB) {
    int bid = blockIdx.x;
    int t = threadIdx.x;

    if (bid < GB) {
        gemm_f16<NFEAT, NHID, 6>(x, W1, g_support1h, N_NODES, bid * 128);
    } else {
        int base = ((bid - GB) * 256 + t) * 4;
#pragma unroll
        for (int u = 0; u < 4; u++) {
            int e = base + u;
            if (e < E) {
                int p = atomicAdd(&g_cur[row[e]], 1);
                int2 packed;
                packed.x = col[e];
                packed.y = __float_as_int(ew[e]);
                g_es[p] = packed;
            }
        }
    }
}

// ---------------- K4: FUSED spmm1(+bias+selu, h1 in smem) + gemm2 ------------
// 128 nodes/block. Phase 1: h1 tile -> As (fp16, stride 104 halves = 208B:
// 16B-aligned rows for ldmatrix, 52-word stride -> conflict-free 8-row sets).
// Phase 2: support2 = As @ W2 via fp16 mma; h1 never touches global memory.
__global__ __launch_bounds__(256)
void mid_kernel(const float* __restrict__ b1, const float* __restrict__ W2) {
    __shared__ __align__(16) __half As[128][104];
    __shared__ __align__(16) __half Bs[64][104];

    const int t = threadIdx.x;
    const int m0 = blockIdx.x * 128;

    // stage W2 [96 x 64] -> Bs[n][k]
    for (int i = t; i < 96 * 64; i += 256) {
        int n = i & 63;
        int k = i >> 6;
        Bs[n][k] = __float2half_rn(W2[k * 64 + n]);
    }

    // ---- Phase 1: spmm1 into smem. 1536 tasks = 128 nodes x 12 chunks(8h) ---
    const uint4* sup = reinterpret_cast<const uint4*>(g_support1h); // 12/row
    const float4* b1v = reinterpret_cast<const float4*>(b1);
    for (int i = 0; i < 6; i++) {
        int task = t + i * 256;
        int r = task / 12;
        int c = task - r * 12;
        int n = m0 + r;
        float acc[8] = {0.f, 0.f, 0.f, 0.f, 0.f, 0.f, 0.f, 0.f};
        if (n < N_NODES) {
            int2 od = g_od[n];
            int off = od.x, deg = od.y;
            int j = 0;
            for (; j + 3 < deg; j += 4) {
                int2 e0 = g_es[off + j];
                int2 e1 = g_es[off + j + 1];
                int2 e2 = g_es[off + j + 2];
                int2 e3 = g_es[off + j + 3];
                uint4 u0 = sup[(size_t)e0.x * 12 + c];
                uint4 u1 = sup[(size_t)e1.x * 12 + c];
                uint4 u2 = sup[(size_t)e2.x * 12 + c];
                uint4 u3 = sup[(size_t)e3.x * 12 + c];
                acc8(acc, u0, __int_as_float(e0.y));
                acc8(acc, u1, __int_as_float(e1.y));
                acc8(acc, u2, __int_as_float(e2.y));
                acc8(acc, u3, __int_as_float(e3.y));
            }
            for (; j < deg; j++) {
                int2 e0 = g_es[off + j];
                uint4 u0 = sup[(size_t)e0.x * 12 + c];
                acc8(acc, u0, __int_as_float(e0.y));
            }
            float4 bb0 = b1v[c * 2];
            float4 bb1 = b1v[c * 2 + 1];
            acc[0] = selu_f(acc[0] + bb0.x); acc[1] = selu_f(acc[1] + bb0.y);
            acc[2] = selu_f(acc[2] + bb0.z); acc[3] = selu_f(acc[3] + bb0.w);
            acc[4] = selu_f(acc[4] + bb1.x); acc[5] = selu_f(acc[5] + bb1.y);
            acc[6] = selu_f(acc[6] + bb1.z); acc[7] = selu_f(acc[7] + bb1.w);
        }
        uint4 val;
        val.x = h2u(__floats2half2_rn(acc[0], acc[1]));
        val.y = h2u(__floats2half2_rn(acc[2], acc[3]));
        val.z = h2u(__floats2half2_rn(acc[4], acc[5]));
        val.w = h2u(__floats2half2_rn(acc[6], acc[7]));
        *reinterpret_cast<uint4*>(
            reinterpret_cast<char*>(&As[0][0]) + r * 208 + c * 16) = val;
    }
    __syncthreads();

    // ---- Phase 2: support2[tile] = As[128x96] @ Bs ---------------------------
    const int lane = t & 31;
    const int wid = t >> 5;
    const int warp_m = wid >> 1;
    const int warp_n = wid & 1;
    const int lq = lane >> 2;
    const int lr = lane & 3;
    const unsigned as_base = (unsigned)__cvta_generic_to_shared(&As[0][0]);
    const unsigned bs_base = (unsigned)__cvta_generic_to_shared(&Bs[0][0]);

    float acc[2][4][4];
#pragma unroll
    for (int i = 0; i < 2; i++)
#pragma unroll
        for (int j = 0; j < 4; j++)
#pragma unroll
            for (int q = 0; q < 4; q++) acc[i][j][q] = 0.f;

#pragma unroll
    for (int ks = 0; ks < 6; ks++) {
        const int k16 = ks * 16;
        unsigned b[4][2];
        const int bl = lane & 15;
        const int brow = bl & 7;
        const int bk = k16 + ((bl >> 3) & 1) * 8;
#pragma unroll
        for (int j = 0; j < 4; j++) {
            unsigned addr = bs_base +
                (unsigned)((warp_n * 32 + j * 8 + brow) * 208 + bk * 2);
            ldsm_x2(addr, b[j][0], b[j][1]);
        }
        const int g = lane >> 3;
        const int rowl = lane & 7;
        const int ar_add = (g & 1) * 8 + rowl;
        const int ak = k16 + (g >> 1) * 8;
#pragma unroll
        for (int i = 0; i < 2; i++) {
            unsigned a[4];
            unsigned addr = as_base +
                (unsigned)((warp_m * 32 + i * 16 + ar_add) * 208 + ak * 2);
            ldsm_x4(addr, a[0], a[1], a[2], a[3]);
#pragma unroll
            for (int j = 0; j < 4; j++) mma_f16(acc[i][j], a, b[j]);
        }
    }

#pragma unroll
    for (int i = 0; i < 2; i++) {
        int r0 = m0 + warp_m * 32 + i * 16 + lq;
#pragma unroll
        for (int j = 0; j < 4; j++) {
            int c0 = warp_n * 32 + j * 8 + 2 * lr;
            if (r0 < N_NODES)
                *reinterpret_cast<__half2*>(g_support2h + (size_t)r0 * 64 + c0) =
                    __floats2half2_rn(acc[i][j][0], acc[i][j][1]);
            if (r0 + 8 < N_NODES)
                *reinterpret_cast<__half2*>(g_support2h + (size_t)(r0 + 8) * 64 + c0) =
                    __floats2half2_rn(acc[i][j][2], acc[i][j][3]);
        }
    }
}

// ---------------- K5: SpMM layer 2 (8-half chunks) + pool + tail head --------
__global__ __launch_bounds__(256)
void spmm2_final_kernel(const float* __restrict__ b2,
                        const float* __restrict__ sub, const float* __restrict__ Wf,
                        const float* __restrict__ bf, const float* __restrict__ gamma,
                        const float* __restrict__ beta, const float* __restrict__ mean,
                        const float* __restrict__ var, float* __restrict__ out) {
    __shared__ float sp[NCLASS];
    __shared__ int s_last;
    int t = threadIdx.x;
    if (t < NCLASS) sp[t] = 0.f;
    __syncthreads();

    int idx = blockIdx.x * 256 + t;
    int n = idx >> 3;          // 8 threads per node
    int c = t & 7;             // chunk of 8 halves
    float r[8] = {0.f, 0.f, 0.f, 0.f, 0.f, 0.f, 0.f, 0.f};

    if (n < N_NODES) {
        int2 od = g_od[n];
        int off = od.x, deg = od.y;
        const uint4* sup = reinterpret_cast<const uint4*>(g_support2h); // 8/row
        float acc[8] = {0.f, 0.f, 0.f, 0.f, 0.f, 0.f, 0.f, 0.f};
        int j = 0;
        for (; j + 3 < deg; j += 4) {
            int2 e0 = g_es[off + j];
            int2 e1 = g_es[off + j + 1];
            int2 e2 = g_es[off + j + 2];
            int2 e3 = g_es[off + j + 3];
            uint4 u0 = sup[(size_t)e0.x * 8 + c];
            uint4 u1 = sup[(size_t)e1.x * 8 + c];
            uint4 u2 = sup[(size_t)e2.x * 8 + c];
            uint4 u3 = sup[(size_t)e3.x * 8 + c];
            acc8(acc, u0, __int_as_float(e0.y));
            acc8(acc, u1, __int_as_float(e1.y));
            acc8(acc, u2, __int_as_float(e2.y));
            acc8(acc, u3, __int_as_float(e3.y));
        }
        for (; j < deg; j++) {
            int2 e0 = g_es[off + j];
            uint4 u0 = sup[(size_t)e0.x * 8 + c];
            acc8(acc, u0, __int_as_float(e0.y));
        }
        const float4* b2v = reinterpret_cast<const float4*>(b2);
        float4 bb0 = b2v[c * 2];
        float4 bb1 = b2v[c * 2 + 1];
        r[0] = selu_f(acc[0] + bb0.x); r[1] = selu_f(acc[1] + bb0.y);
        r[2] = selu_f(acc[2] + bb0.z); r[3] = selu_f(acc[3] + bb0.w);
        r[4] = selu_f(acc[4] + bb1.x); r[5] = selu_f(acc[5] + bb1.y);
        r[6] = selu_f(acc[6] + bb1.z); r[7] = selu_f(acc[7] + bb1.w);
    }

    // lanes t, t^8, t^16, t^24 share chunk c (different nodes)
#pragma unroll
    for (int q = 0; q < 8; q++) {
        r[q] += __shfl_xor_sync(0xffffffffu, r[q], 8);
        r[q] += __shfl_xor_sync(0xffffffffu, r[q], 16);
    }
    if ((t & 24) == 0) {
#pragma unroll
        for (int q = 0; q < 8; q++) atomicAdd(&sp[c * 8 + q], r[q]);
    }
    __syncthreads();
    if (t < NCLASS) atomicAdd(&g_pool[t], sp[t]);

    __threadfence();
    __syncthreads();
    if (t == 0) s_last = (atomicAdd(&g_done, 1) == (int)gridDim.x - 1);
    __syncthreads();
    if (!s_last) return;
    __threadfence();

    __shared__ float z[NCLASS + NEXT];
    __shared__ float logits[NCLASS];
    __shared__ float red[256];
    __shared__ float s_max, s_lse;

    if (t < NCLASS) {
        z[t] = selu_f(__ldcg(&g_pool[t]) / (float)N_NODES);
    } else if (t < NCLASS + NEXT) {
        int jj = t - NCLASS;
        z[t] = (sub[jj] - mean[jj]) * rsqrtf(var[jj] + BN_EPS) * gamma[jj] + beta[jj];
    }
    __syncthreads();

    if (t < NCLASS) {
        float a = bf[t];
        const float* wrow = Wf + (size_t)t * (NCLASS + NEXT);
#pragma unroll
        for (int k = 0; k < NCLASS + NEXT; k++) a += z[k] * wrow[k];
        logits[t] = a;
    }
    __syncthreads();

    if (t == 0) {
        float m = -INFINITY;
        for (int k = 0; k < NCLASS; k++) m = fmaxf(m, logits[k]);
        float s = 0.f;
        for (int k = 0; k < NCLASS; k++) s += expf(logits[k] - m);
        s_max = m;
        s_lse = logf(s);
    }
    __syncthreads();
    if (t < NCLASS) out[t] = logits[t] - s_max - s_lse;

    float l = 0.f;
    const int TOTW = NCLASS * (NCLASS + NEXT);
    for (int i = t; i < TOTW; i += 256) l += fabsf(Wf[i]);
    red[t] = l;
    __syncthreads();
    for (int s2 = 128; s2 > 0; s2 >>= 1) {
        if (t < s2) red[t] += red[t + s2];
        __syncthreads();
    }
    if (t == 0) out[NCLASS] = red[0] / (float)TOTW;

    // restore invariants
    if (t < NCLASS) g_pool[t] = 0.f;
    if (t == 0) { g_done = 0; g_total = 0; }
}

// ---------------- launch -----------------------------------------------------
extern "C" void kernel_launch(void* const* d_in, const int* in_sizes, int n_in,
                              void* d_out, int out_size) {
    const float* x     = (const float*)d_in[0];
    const int*   row   = (const int*)  d_in[1];
    const int*   col   = (const int*)  d_in[2];
    const float* ew    = (const float*)d_in[3];
    const float* sub   = (const float*)d_in[4];
    const float* W1    = (const float*)d_in[5];
    const float* b1    = (const float*)d_in[6];
    const float* W2    = (const float*)d_in[7];
    const float* b2    = (const float*)d_in[8];
    const float* Wf    = (const float*)d_in[9];
    const float* bf    = (const float*)d_in[10];
    const float* gamma = (const float*)d_in[11];
    const float* beta  = (const float*)d_in[12];
    const float* mean  = (const float*)d_in[13];
    const float* var   = (const float*)d_in[14];
    float* out = (float*)d_out;

    const int E = (n_in > 1) ? in_sizes[1] : N_EDGES;

    const int GB  = (N_NODES + 127) / 128;   // 391 tile blocks
    const int SCB = (E + 1023) / 1024;       // scatter blocks

    hist_kernel<<<(E + 255) / 256, 256>>>(row, E);
    alloc_kernel<<<(N_NODES + 255) / 256, 256>>>();
    fat1_kernel<<<GB + SCB, 256>>>(x, W1, row, col, ew, E, GB);
    mid_kernel<<<GB, 256>>>(b1, W2);
    spmm2_final_kernel<<<(N_NODES * 8 + 255) / 256, 256>>>(
        b2, sub, Wf, bf, gamma, beta, mean, var, out);
}

// round 13
// speedup vs baseline: 1.4167x; 1.0094x over previous
#include <cuda_runtime.h>
#include <cuda_fp16.h>
#include <math.h>

#define N_NODES 50000
#define N_EDGES 800000
#define NFEAT 128
#define NHID 96
#define NCLASS 64
#define NEXT 32
#define BN_EPS 1e-5f

// ---------------- scratch (device globals; zero-initialized at load) --------
// Invariant at entry/exit: g_cnt == 0, g_pool == 0, g_done == 0, g_total == 0.
__device__ __align__(16) __half g_support1h[N_NODES * NHID];   // x@W1 (fp16)
__device__ __align__(16) __half g_support2h[N_NODES * NCLASS]; // h2 pre-agg (fp16)
__device__ float g_pool[NCLASS];
__device__ int   g_done;
__device__ int   g_total;

__device__ int  g_cnt[N_NODES];
__device__ int2 g_od[N_NODES];                 // (offset, degree) per node
__device__ int  g_cur[N_NODES];
__device__ int2 g_es[N_EDGES];                 // packed (col, w) grouped by row

// ---------------- helpers ----------------------------------------------------
__device__ __forceinline__ float selu_f(float v) {
    const float scale = 1.0507009873554805f;
    const float alpha = 1.6732632423543772f;
    return scale * (v > 0.0f ? v : alpha * (expf(v) - 1.0f));
}

__device__ __forceinline__ void ldsm_x4(unsigned addr, unsigned& r0, unsigned& r1,
                                        unsigned& r2, unsigned& r3) {
    asm volatile("ldmatrix.sync.aligned.m8n8.x4.shared.b16 {%0,%1,%2,%3}, [%4];"
                 : "=r"(r0), "=r"(r1), "=r"(r2), "=r"(r3) : "r"(addr));
}

__device__ __forceinline__ void ldsm_x2(unsigned addr, unsigned& r0, unsigned& r1) {
    asm volatile("ldmatrix.sync.aligned.m8n8.x2.shared.b16 {%0,%1}, [%2];"
                 : "=r"(r0), "=r"(r1) : "r"(addr));
}

__device__ __forceinline__ void mma_f16(float c[4], const unsigned a[4],
                                        const unsigned b[2]) {
    asm volatile(
        "mma.sync.aligned.m16n8k16.row.col.f32.f16.f16.f32 "
        "{%0,%1,%2,%3}, {%4,%5,%6,%7}, {%8,%9}, {%0,%1,%2,%3};"
        : "+f"(c[0]), "+f"(c[1]), "+f"(c[2]), "+f"(c[3])
        : "r"(a[0]), "r"(a[1]), "r"(a[2]), "r"(a[3]), "r"(b[0]), "r"(b[1]));
}

__device__ __forceinline__ unsigned h2u(__half2 h) {
    return *reinterpret_cast<unsigned*>(&h);
}

// accumulate 8 halves (uint4) * w into acc[8]
__device__ __forceinline__ void acc8(float acc[8], uint4 u, float w) {
    float2 p0 = __half22float2(*reinterpret_cast<__half2*>(&u.x));
    float2 p1 = __half22float2(*reinterpret_cast<__half2*>(&u.y));
    float2 p2 = __half22float2(*reinterpret_cast<__half2*>(&u.z));
    float2 p3 = __half22float2(*reinterpret_cast<__half2*>(&u.w));
    acc[0] += w * p0.x; acc[1] += w * p0.y;
    acc[2] += w * p1.x; acc[3] += w * p1.y;
    acc[4] += w * p2.x; acc[5] += w * p2.y;
    acc[6] += w * p3.x; acc[7] += w * p3.y;
}

// ---------------- K1: histogram ----------------------------------------------
__global__ void hist_kernel(const int* __restrict__ row, int E) {
    int e = blockIdx.x * blockDim.x + threadIdx.x;
    if (e < E) atomicAdd(&g_cnt[row[e]], 1);
}

// ---------------- K2: unordered CSR allocation -------------------------------
__global__ __launch_bounds__(256)
void alloc_kernel() {
    int i = blockIdx.x * 256 + threadIdx.x;
    int lane = threadIdx.x & 31;
    int cnt = (i < N_NODES) ? g_cnt[i] : 0;
    int incl = cnt;
#pragma unroll
    for (int d = 1; d < 32; d <<= 1) {
        int v = __shfl_up_sync(0xffffffffu, incl, d);
        if (lane >= d) incl += v;
    }
    int total = __shfl_sync(0xffffffffu, incl, 31);
    int base = 0;
    if (lane == 0) base = atomicAdd(&g_total, total);
    base = __shfl_sync(0xffffffffu, base, 0);
    if (i < N_NODES) {
        int off = base + incl - cnt;
        g_od[i] = make_int2(off, cnt);
        g_cur[i] = off;
        g_cnt[i] = 0;
    }
}

// ---------------- fp16 tensor-core GEMM tile (for gemm1, stride 40) ----------
template <int K, int N, int NT>
__device__ __forceinline__
void gemm_f16(const float* __restrict__ A, const float* __restrict__ W,
              __half* __restrict__ C, int M, int m0) {
    __shared__ __align__(16) __half As[128][40];
    __shared__ __align__(16) __half Bs[N][40];

    const int t = threadIdx.x;
    const int lane = t & 31;
    const int wid = t >> 5;
    const int warp_m = wid >> 1;
    const int warp_n = wid & 1;
    const int lq = lane >> 2;
    const int lr = lane & 3;

    const unsigned as_base = (unsigned)__cvta_generic_to_shared(&As[0][0]);
    const unsigned bs_base = (unsigned)__cvta_generic_to_shared(&Bs[0][0]);

    float acc[2][NT][4];
#pragma unroll
    for (int i = 0; i < 2; i++)
#pragma unroll
        for (int j = 0; j < NT; j++)
#pragma unroll
            for (int q = 0; q < 4; q++) acc[i][j][q] = 0.f;

    const int arow = t >> 1;
    const int ah = (t & 1) * 16;

    for (int kk = 0; kk < K; kk += 32) {
#pragma unroll
        for (int q = 0; q < 4; q++) {
            int kq = ah + q * 4;
            float4 v = make_float4(0.f, 0.f, 0.f, 0.f);
            if (m0 + arow < M)
                v = *reinterpret_cast<const float4*>(A + (size_t)(m0 + arow) * K + kk + kq);
            uint2 u;
            u.x = h2u(__floats2half2_rn(v.x, v.y));
            u.y = h2u(__floats2half2_rn(v.z, v.w));
            *reinterpret_cast<uint2*>(
                reinterpret_cast<char*>(&As[0][0]) + arow * 80 + kq * 2) = u;
        }
#pragma unroll
        for (int r = 0; r < (32 * N) / 256; r++) {
            int i = t + r * 256;
            int k = i / N;
            int n = i - k * N;
            Bs[n][k] = __float2half_rn(W[(size_t)(kk + k) * N + n]);
        }
        __syncthreads();

#pragma unroll
        for (int ks = 0; ks < 2; ks++) {
            const int k16 = ks * 16;
            unsigned b[NT][2];
            const int bl = lane & 15;
            const int brow = bl & 7;
            const int bk = k16 + ((bl >> 3) & 1) * 8;
#pragma unroll
            for (int j = 0; j < NT; j++) {
                unsigned addr = bs_base +
                    (unsigned)((warp_n * (NT * 8) + j * 8 + brow) * 80 + bk * 2);
                ldsm_x2(addr, b[j][0], b[j][1]);
            }
            const int g = lane >> 3;
            const int rowl = lane & 7;
            const int ar_add = (g & 1) * 8 + rowl;
            const int ak = k16 + (g >> 1) * 8;
#pragma unroll
            for (int i = 0; i < 2; i++) {
                unsigned a[4];
                unsigned addr = as_base +
                    (unsigned)((warp_m * 32 + i * 16 + ar_add) * 80 + ak * 2);
                ldsm_x4(addr, a[0], a[1], a[2], a[3]);
#pragma unroll
                for (int j = 0; j < NT; j++) mma_f16(acc[i][j], a, b[j]);
            }
        }
        __syncthreads();
    }

#pragma unroll
    for (int i = 0; i < 2; i++) {
        int r0 = m0 + warp_m * 32 + i * 16 + lq;
#pragma unroll
        for (int j = 0; j < NT; j++) {
            int c0 = warp_n * (NT * 8) + j * 8 + 2 * lr;
            if (r0 < M)
                *reinterpret_cast<__half2*>(C + (size_t)r0 * N + c0) =
                    __floats2half2_rn(acc[i][j][0], acc[i][j][1]);
            if (r0 + 8 < M)
                *reinterpret_cast<__half2*>(C + (size_t)(r0 + 8) * N + c0) =
                    __floats2half2_rn(acc[i][j][2], acc[i][j][3]);
        }
    }
}

// ---------------- K3: fat kernel — gemm1(fp16 mma) || scatter ----------------
__global__ __launch_bounds__(256)
void fat1_kernel(const float* __restrict__ x, const float* __restrict__ W1,
                 const int* __restrict__ row, const int* __restrict__ col,
                 const float* __restrict__ ew, int E, int GB) {
    int bid = blockIdx.x;
    int t = threadIdx.x;

    if (bid < GB) {
        gemm_f16<NFEAT, NHID, 6>(x, W1, g_support1h, N_NODES, bid * 128);
    } else {
        int base = ((bid - GB) * 256 + t) * 4;
#pragma unroll
        for (int u = 0; u < 4; u++) {
            int e = base + u;
            if (e < E) {
                int p = atomicAdd(&g_cur[row[e]], 1);
                int2 packed;
                packed.x = col[e];
                packed.y = __float_as_int(ew[e]);
                g_es[p] = packed;
            }
        }
    }
}

// ---------------- K4: FUSED spmm1(+bias+selu, h1 in smem) + gemm2 ------------
// 64 nodes/block (782 blocks): 26 KB smem -> higher residency + finer load
// balance for the latency-bound gather phase. Phase 1: h1 tile -> As (fp16,
// stride 104 halves = 208B: 16B-aligned rows, conflict-free ldmatrix sets).
// Phase 2: support2 tile = As[64x96] @ W2 via fp16 mma.
__global__ __launch_bounds__(256)
void mid_kernel(const float* __restrict__ b1, const float* __restrict__ W2) {
    __shared__ __align__(16) __half As[64][104];
    __shared__ __align__(16) __half Bs[64][104];

    const int t = threadIdx.x;
    const int m0 = blockIdx.x * 64;

    // stage W2 [96 x 64] -> Bs[n][k]
    for (int i = t; i < 96 * 64; i += 256) {
        int n = i & 63;
        int k = i >> 6;
        Bs[n][k] = __float2half_rn(W2[k * 64 + n]);
    }

    // ---- Phase 1: spmm1 into smem. 768 tasks = 64 nodes x 12 chunks(8h) -----
    const uint4* sup = reinterpret_cast<const uint4*>(g_support1h); // 12/row
    const float4* b1v = reinterpret_cast<const float4*>(b1);
#pragma unroll
    for (int i = 0; i < 3; i++) {
        int task = t + i * 256;
        int r = task / 12;
        int c = task - r * 12;
        int n = m0 + r;
        float acc[8] = {0.f, 0.f, 0.f, 0.f, 0.f, 0.f, 0.f, 0.f};
        if (n < N_NODES) {
            int2 od = g_od[n];
            int off = od.x, deg = od.y;
            int j = 0;
            for (; j + 3 < deg; j += 4) {
                int2 e0 = g_es[off + j];
                int2 e1 = g_es[off + j + 1];
                int2 e2 = g_es[off + j + 2];
                int2 e3 = g_es[off + j + 3];
                uint4 u0 = sup[(size_t)e0.x * 12 + c];
                uint4 u1 = sup[(size_t)e1.x * 12 + c];
                uint4 u2 = sup[(size_t)e2.x * 12 + c];
                uint4 u3 = sup[(size_t)e3.x * 12 + c];
                acc8(acc, u0, __int_as_float(e0.y));
                acc8(acc, u1, __int_as_float(e1.y));
                acc8(acc, u2, __int_as_float(e2.y));
                acc8(acc, u3, __int_as_float(e3.y));
            }
            for (; j < deg; j++) {
                int2 e0 = g_es[off + j];
                uint4 u0 = sup[(size_t)e0.x * 12 + c];
                acc8(acc, u0, __int_as_float(e0.y));
            }
            float4 bb0 = b1v[c * 2];
            float4 bb1 = b1v[c * 2 + 1];
            acc[0] = selu_f(acc[0] + bb0.x); acc[1] = selu_f(acc[1] + bb0.y);
            acc[2] = selu_f(acc[2] + bb0.z); acc[3] = selu_f(acc[3] + bb0.w);
            acc[4] = selu_f(acc[4] + bb1.x); acc[5] = selu_f(acc[5] + bb1.y);
            acc[6] = selu_f(acc[6] + bb1.z); acc[7] = selu_f(acc[7] + bb1.w);
        }
        uint4 val;
        val.x = h2u(__floats2half2_rn(acc[0], acc[1]));
        val.y = h2u(__floats2half2_rn(acc[2], acc[3]));
        val.z = h2u(__floats2half2_rn(acc[4], acc[5]));
        val.w = h2u(__floats2half2_rn(acc[6], acc[7]));
        *reinterpret_cast<uint4*>(
            reinterpret_cast<char*>(&As[0][0]) + r * 208 + c * 16) = val;
    }
    __syncthreads();

    // ---- Phase 2: support2[tile] = As[64x96] @ Bs ---------------------------
    // 8 warps as 4(m) x 2(n); each warp: one 16-row m-fragment, 4 n-tiles.
    const int lane = t & 31;
    const int wid = t >> 5;
    const int warp_m = wid >> 1;        // 0..3 -> 16 rows each
    const int warp_n = wid & 1;         // 0..1
    const int lq = lane >> 2;
    const int lr = lane & 3;
    const unsigned as_base = (unsigned)__cvta_generic_to_shared(&As[0][0]);
    const unsigned bs_base = (unsigned)__cvta_generic_to_shared(&Bs[0][0]);

    float acc[4][4];
#pragma unroll
    for (int j = 0; j < 4; j++)
#pragma unroll
        for (int q = 0; q < 4; q++) acc[j][q] = 0.f;

#pragma unroll
    for (int ks = 0; ks < 6; ks++) {
        const int k16 = ks * 16;
        unsigned b[4][2];
        const int bl = lane & 15;
        const int brow = bl & 7;
        const int bk = k16 + ((bl >> 3) & 1) * 8;
#pragma unroll
        for (int j = 0; j < 4; j++) {
            unsigned addr = bs_base +
                (unsigned)((warp_n * 32 + j * 8 + brow) * 208 + bk * 2);
            ldsm_x2(addr, b[j][0], b[j][1]);
        }
        const int g = lane >> 3;
        const int rowl = lane & 7;
        const int ar_add = (g & 1) * 8 + rowl;
        const int ak = k16 + (g >> 1) * 8;
        unsigned a[4];
        unsigned addr = as_base +
            (unsigned)((warp_m * 16 + ar_add) * 208 + ak * 2);
        ldsm_x4(addr, a[0], a[1], a[2], a[3]);
#pragma unroll
        for (int j = 0; j < 4; j++) mma_f16(acc[j], a, b[j]);
    }

    int r0 = m0 + warp_m * 16 + lq;
#pragma unroll
    for (int j = 0; j < 4; j++) {
        int c0 = warp_n * 32 + j * 8 + 2 * lr;
        if (r0 < N_NODES)
            *reinterpret_cast<__half2*>(g_support2h + (size_t)r0 * 64 + c0) =
                __floats2half2_rn(acc[j][0], acc[j][1]);
        if (r0 + 8 < N_NODES)
            *reinterpret_cast<__half2*>(g_support2h + (size_t)(r0 + 8) * 64 + c0) =
                __floats2half2_rn(acc[j][2], acc[j][3]);
    }
}

// ---------------- K5: SpMM layer 2 (8-half chunks) + pool + tail head --------
__global__ __launch_bounds__(256)
void spmm2_final_kernel(const float* __restrict__ b2,
                        const float* __restrict__ sub, const float* __restrict__ Wf,
                        const float* __restrict__ bf, const float* __restrict__ gamma,
                        const float* __restrict__ beta, const float* __restrict__ mean,
                        const float* __restrict__ var, float* __restrict__ out) {
    __shared__ float sp[NCLASS];
    __shared__ int s_last;
    int t = threadIdx.x;
    if (t < NCLASS) sp[t] = 0.f;
    __syncthreads();

    int idx = blockIdx.x * 256 + t;
    int n = idx >> 3;          // 8 threads per node
    int c = t & 7;             // chunk of 8 halves
    float r[8] = {0.f, 0.f, 0.f, 0.f, 0.f, 0.f, 0.f, 0.f};

    if (n < N_NODES) {
        int2 od = g_od[n];
        int off = od.x, deg = od.y;
        const uint4* sup = reinterpret_cast<const uint4*>(g_support2h); // 8/row
        float acc[8] = {0.f, 0.f, 0.f, 0.f, 0.f, 0.f, 0.f, 0.f};
        int j = 0;
        for (; j + 3 < deg; j += 4) {
            int2 e0 = g_es[off + j];
            int2 e1 = g_es[off + j + 1];
            int2 e2 = g_es[off + j + 2];
            int2 e3 = g_es[off + j + 3];
            uint4 u0 = sup[(size_t)e0.x * 8 + c];
            uint4 u1 = sup[(size_t)e1.x * 8 + c];
            uint4 u2 = sup[(size_t)e2.x * 8 + c];
            uint4 u3 = sup[(size_t)e3.x * 8 + c];
            acc8(acc, u0, __int_as_float(e0.y));
            acc8(acc, u1, __int_as_float(e1.y));
            acc8(acc, u2, __int_as_float(e2.y));
            acc8(acc, u3, __int_as_float(e3.y));
        }
        for (; j < deg; j++) {
            int2 e0 = g_es[off + j];
            uint4 u0 = sup[(size_t)e0.x * 8 + c];
            acc8(acc, u0, __int_as_float(e0.y));
        }
        const float4* b2v = reinterpret_cast<const float4*>(b2);
        float4 bb0 = b2v[c * 2];
        float4 bb1 = b2v[c * 2 + 1];
        r[0] = selu_f(acc[0] + bb0.x); r[1] = selu_f(acc[1] + bb0.y);
        r[2] = selu_f(acc[2] + bb0.z); r[3] = selu_f(acc[3] + bb0.w);
        r[4] = selu_f(acc[4] + bb1.x); r[5] = selu_f(acc[5] + bb1.y);
        r[6] = selu_f(acc[6] + bb1.z); r[7] = selu_f(acc[7] + bb1.w);
    }

    // lanes t, t^8, t^16, t^24 share chunk c (different nodes)
#pragma unroll
    for (int q = 0; q < 8; q++) {
        r[q] += __shfl_xor_sync(0xffffffffu, r[q], 8);
        r[q] += __shfl_xor_sync(0xffffffffu, r[q], 16);
    }
    if ((t & 24) == 0) {
#pragma unroll
        for (int q = 0; q < 8; q++) atomicAdd(&sp[c * 8 + q], r[q]);
    }
    __syncthreads();
    if (t < NCLASS) atomicAdd(&g_pool[t], sp[t]);

    __threadfence();
    __syncthreads();
    if (t == 0) s_last = (atomicAdd(&g_done, 1) == (int)gridDim.x - 1);
    __syncthreads();
    if (!s_last) return;
    __threadfence();

    __shared__ float z[NCLASS + NEXT];
    __shared__ float logits[NCLASS];
    __shared__ float red[256];
    __shared__ float s_max, s_lse;

    if (t < NCLASS) {
        z[t] = selu_f(__ldcg(&g_pool[t]) / (float)N_NODES);
    } else if (t < NCLASS + NEXT) {
        int jj = t - NCLASS;
        z[t] = (sub[jj] - mean[jj]) * rsqrtf(var[jj] + BN_EPS) * gamma[jj] + beta[jj];
    }
    __syncthreads();

    if (t < NCLASS) {
        float a = bf[t];
        const float* wrow = Wf + (size_t)t * (NCLASS + NEXT);
#pragma unroll
        for (int k = 0; k < NCLASS + NEXT; k++) a += z[k] * wrow[k];
        logits[t] = a;
    }
    __syncthreads();

    if (t == 0) {
        float m = -INFINITY;
        for (int k = 0; k < NCLASS; k++) m = fmaxf(m, logits[k]);
        float s = 0.f;
        for (int k = 0; k < NCLASS; k++) s += expf(logits[k] - m);
        s_max = m;
        s_lse = logf(s);
    }
    __syncthreads();
    if (t < NCLASS) out[t] = logits[t] - s_max - s_lse;

    float l = 0.f;
    const int TOTW = NCLASS * (NCLASS + NEXT);
    for (int i = t; i < TOTW; i += 256) l += fabsf(Wf[i]);
    red[t] = l;
    __syncthreads();
    for (int s2 = 128; s2 > 0; s2 >>= 1) {
        if (t < s2) red[t] += red[t + s2];
        __syncthreads();
    }
    if (t == 0) out[NCLASS] = red[0] / (float)TOTW;

    // restore invariants
    if (t < NCLASS) g_pool[t] = 0.f;
    if (t == 0) { g_done = 0; g_total = 0; }
}

// ---------------- launch -----------------------------------------------------
extern "C" void kernel_launch(void* const* d_in, const int* in_sizes, int n_in,
                              void* d_out, int out_size) {
    const float* x     = (const float*)d_in[0];
    const int*   row   = (const int*)  d_in[1];
    const int*   col   = (const int*)  d_in[2];
    const float* ew    = (const float*)d_in[3];
    const float* sub   = (const float*)d_in[4];
    const float* W1    = (const float*)d_in[5];
    const float* b1    = (const float*)d_in[6];
    const float* W2    = (const float*)d_in[7];
    const float* b2    = (const float*)d_in[8];
    const float* Wf    = (const float*)d_in[9];
    const float* bf    = (const float*)d_in[10];
    const float* gamma = (const float*)d_in[11];
    const float* beta  = (const float*)d_in[12];
    const float* mean  = (const float*)d_in[13];
    const float* var   = (const float*)d_in[14];
    float* out = (float*)d_out;

    const int E = (n_in > 1) ? in_sizes[1] : N_EDGES;

    const int GB  = (N_NODES + 127) / 128;   // 391 gemm1 tile blocks
    const int MB  = (N_NODES + 63) / 64;     // 782 mid tile blocks
    const int SCB = (E + 1023) / 1024;       // scatter blocks

    hist_kernel<<<(E + 255) / 256, 256>>>(row, E);
    alloc_kernel<<<(N_NODES + 255) / 256, 256>>>();
    fat1_kernel<<<GB + SCB, 256>>>(x, W1, row, col, ew, E, GB);
    mid_kernel<<<MB, 256>>>(b1, W2);
    spmm2_final_kernel<<<(N_NODES * 8 + 255) / 256, 256>>>(
        b2, sub, Wf, bf, gamma, beta, mean, var, out);
}

// round 14
// speedup vs baseline: 1.5106x; 1.0663x over previous
#include <cuda_runtime.h>
#include <cuda_fp16.h>
#include <math.h>

#define N_NODES 50000
#define N_EDGES 800000
#define NFEAT 128
#define NHID 96
#define NCLASS 64
#define NEXT 32
#define BN_EPS 1e-5f

// ---------------- scratch (device globals; zero-initialized at load) --------
// Invariant at entry/exit: g_cnt == 0, g_pool == 0, g_done == 0, g_total == 0.
__device__ __align__(16) __half g_support1h[N_NODES * NHID];   // x@W1 (fp16)
__device__ __align__(16) __half g_support2h[N_NODES * NCLASS]; // h2 pre-agg (fp16)
__device__ float g_pool[NCLASS];
__device__ int   g_done;
__device__ int   g_total;

__device__ int  g_cnt[N_NODES];
__device__ int2 g_od[N_NODES];                 // (offset, degree) per node
__device__ int  g_cur[N_NODES];
__device__ int2 g_es[N_EDGES];                 // packed (col, w) grouped by row

// ---------------- helpers ----------------------------------------------------
__device__ __forceinline__ float selu_f(float v) {
    const float scale = 1.0507009873554805f;
    const float alpha = 1.6732632423543772f;
    return scale * (v > 0.0f ? v : alpha * (expf(v) - 1.0f));
}

__device__ __forceinline__ void ldsm_x4(unsigned addr, unsigned& r0, unsigned& r1,
                                        unsigned& r2, unsigned& r3) {
    asm volatile("ldmatrix.sync.aligned.m8n8.x4.shared.b16 {%0,%1,%2,%3}, [%4];"
                 : "=r"(r0), "=r"(r1), "=r"(r2), "=r"(r3) : "r"(addr));
}

__device__ __forceinline__ void ldsm_x2(unsigned addr, unsigned& r0, unsigned& r1) {
    asm volatile("ldmatrix.sync.aligned.m8n8.x2.shared.b16 {%0,%1}, [%2];"
                 : "=r"(r0), "=r"(r1) : "r"(addr));
}

__device__ __forceinline__ void mma_f16(float c[4], const unsigned a[4],
                                        const unsigned b[2]) {
    asm volatile(
        "mma.sync.aligned.m16n8k16.row.col.f32.f16.f16.f32 "
        "{%0,%1,%2,%3}, {%4,%5,%6,%7}, {%8,%9}, {%0,%1,%2,%3};"
        : "+f"(c[0]), "+f"(c[1]), "+f"(c[2]), "+f"(c[3])
        : "r"(a[0]), "r"(a[1]), "r"(a[2]), "r"(a[3]), "r"(b[0]), "r"(b[1]));
}

__device__ __forceinline__ unsigned h2u(__half2 h) {
    return *reinterpret_cast<unsigned*>(&h);
}

// accumulate 8 halves (uint4) * w2 into 4 half2 accumulators (HFMA2 path)
__device__ __forceinline__ void acc8h(__half2 acc[4], uint4 u, __half2 w2) {
    acc[0] = __hfma2(*reinterpret_cast<__half2*>(&u.x), w2, acc[0]);
    acc[1] = __hfma2(*reinterpret_cast<__half2*>(&u.y), w2, acc[1]);
    acc[2] = __hfma2(*reinterpret_cast<__half2*>(&u.z), w2, acc[2]);
    acc[3] = __hfma2(*reinterpret_cast<__half2*>(&u.w), w2, acc[3]);
}

// ---------------- K1: histogram ----------------------------------------------
__global__ void hist_kernel(const int* __restrict__ row, int E) {
    int e = blockIdx.x * blockDim.x + threadIdx.x;
    if (e < E) atomicAdd(&g_cnt[row[e]], 1);
}

// ---------------- K2: unordered CSR allocation -------------------------------
__global__ __launch_bounds__(256)
void alloc_kernel() {
    int i = blockIdx.x * 256 + threadIdx.x;
    int lane = threadIdx.x & 31;
    int cnt = (i < N_NODES) ? g_cnt[i] : 0;
    int incl = cnt;
#pragma unroll
    for (int d = 1; d < 32; d <<= 1) {
        int v = __shfl_up_sync(0xffffffffu, incl, d);
        if (lane >= d) incl += v;
    }
    int total = __shfl_sync(0xffffffffu, incl, 31);
    int base = 0;
    if (lane == 0) base = atomicAdd(&g_total, total);
    base = __shfl_sync(0xffffffffu, base, 0);
    if (i < N_NODES) {
        int off = base + incl - cnt;
        g_od[i] = make_int2(off, cnt);
        g_cur[i] = off;
        g_cnt[i] = 0;
    }
}

// ---------------- fp16 tensor-core GEMM tile (for gemm1, stride 40) ----------
template <int K, int N, int NT>
__device__ __forceinline__
void gemm_f16(const float* __restrict__ A, const float* __restrict__ W,
              __half* __restrict__ C, int M, int m0) {
    __shared__ __align__(16) __half As[128][40];
    __shared__ __align__(16) __half Bs[N][40];

    const int t = threadIdx.x;
    const int lane = t & 31;
    const int wid = t >> 5;
    const int warp_m = wid >> 1;
    const int warp_n = wid & 1;
    const int lq = lane >> 2;
    const int lr = lane & 3;

    const unsigned as_base = (unsigned)__cvta_generic_to_shared(&As[0][0]);
    const unsigned bs_base = (unsigned)__cvta_generic_to_shared(&Bs[0][0]);

    float acc[2][NT][4];
#pragma unroll
    for (int i = 0; i < 2; i++)
#pragma unroll
        for (int j = 0; j < NT; j++)
#pragma unroll
            for (int q = 0; q < 4; q++) acc[i][j][q] = 0.f;

    const int arow = t >> 1;
    const int ah = (t & 1) * 16;

    for (int kk = 0; kk < K; kk += 32) {
#pragma unroll
        for (int q = 0; q < 4; q++) {
            int kq = ah + q * 4;
            float4 v = make_float4(0.f, 0.f, 0.f, 0.f);
            if (m0 + arow < M)
                v = *reinterpret_cast<const float4*>(A + (size_t)(m0 + arow) * K + kk + kq);
            uint2 u;
            u.x = h2u(__floats2half2_rn(v.x, v.y));
            u.y = h2u(__floats2half2_rn(v.z, v.w));
            *reinterpret_cast<uint2*>(
                reinterpret_cast<char*>(&As[0][0]) + arow * 80 + kq * 2) = u;
        }
#pragma unroll
        for (int r = 0; r < (32 * N) / 256; r++) {
            int i = t + r * 256;
            int k = i / N;
            int n = i - k * N;
            Bs[n][k] = __float2half_rn(W[(size_t)(kk + k) * N + n]);
        }
        __syncthreads();

#pragma unroll
        for (int ks = 0; ks < 2; ks++) {
            const int k16 = ks * 16;
            unsigned b[NT][2];
            const int bl = lane & 15;
            const int brow = bl & 7;
            const int bk = k16 + ((bl >> 3) & 1) * 8;
#pragma unroll
            for (int j = 0; j < NT; j++) {
                unsigned addr = bs_base +
                    (unsigned)((warp_n * (NT * 8) + j * 8 + brow) * 80 + bk * 2);
                ldsm_x2(addr, b[j][0], b[j][1]);
            }
            const int g = lane >> 3;
            const int rowl = lane & 7;
            const int ar_add = (g & 1) * 8 + rowl;
            const int ak = k16 + (g >> 1) * 8;
#pragma unroll
            for (int i = 0; i < 2; i++) {
                unsigned a[4];
                unsigned addr = as_base +
                    (unsigned)((warp_m * 32 + i * 16 + ar_add) * 80 + ak * 2);
                ldsm_x4(addr, a[0], a[1], a[2], a[3]);
#pragma unroll
                for (int j = 0; j < NT; j++) mma_f16(acc[i][j], a, b[j]);
            }
        }
        __syncthreads();
    }

#pragma unroll
    for (int i = 0; i < 2; i++) {
        int r0 = m0 + warp_m * 32 + i * 16 + lq;
#pragma unroll
        for (int j = 0; j < NT; j++) {
            int c0 = warp_n * (NT * 8) + j * 8 + 2 * lr;
            if (r0 < M)
                *reinterpret_cast<__half2*>(C + (size_t)r0 * N + c0) =
                    __floats2half2_rn(acc[i][j][0], acc[i][j][1]);
            if (r0 + 8 < M)
                *reinterpret_cast<__half2*>(C + (size_t)(r0 + 8) * N + c0) =
                    __floats2half2_rn(acc[i][j][2], acc[i][j][3]);
        }
    }
}

// ---------------- K3: fat kernel — gemm1(fp16 mma) || scatter ----------------
__global__ __launch_bounds__(256)
void fat1_kernel(const float* __restrict__ x, const float* __restrict__ W1,
                 const int* __restrict__ row, const int* __restrict__ col,
                 const float* __restrict__ ew, int E, int GB) {
    int bid = blockIdx.x;
    int t = threadIdx.x;

    if (bid < GB) {
        gemm_f16<NFEAT, NHID, 6>(x, W1, g_support1h, N_NODES, bid * 128);
    } else {
        int base = ((bid - GB) * 256 + t) * 4;
#pragma unroll
        for (int u = 0; u < 4; u++) {
            int e = base + u;
            if (e < E) {
                int p = atomicAdd(&g_cur[row[e]], 1);
                int2 packed;
                packed.x = col[e];
                packed.y = __float_as_int(ew[e]);
                g_es[p] = packed;
            }
        }
    }
}

// ---------------- K4: FUSED spmm1(+bias+selu, h1 in smem) + gemm2 ------------
// 64 nodes/block; gather accumulates in half2 (HFMA2), converts to fp32 only
// for bias+selu. Phase 2: support2 tile = As[64x96] @ W2 via fp16 mma.
__global__ __launch_bounds__(256)
void mid_kernel(const float* __restrict__ b1, const float* __restrict__ W2) {
    __shared__ __align__(16) __half As[64][104];
    __shared__ __align__(16) __half Bs[64][104];

    const int t = threadIdx.x;
    const int m0 = blockIdx.x * 64;

    // stage W2 [96 x 64] -> Bs[n][k]
    for (int i = t; i < 96 * 64; i += 256) {
        int n = i & 63;
        int k = i >> 6;
        Bs[n][k] = __float2half_rn(W2[k * 64 + n]);
    }

    // ---- Phase 1: spmm1 into smem. 768 tasks = 64 nodes x 12 chunks(8h) -----
    const uint4* sup = reinterpret_cast<const uint4*>(g_support1h); // 12/row
    const float4* b1v = reinterpret_cast<const float4*>(b1);
#pragma unroll
    for (int i = 0; i < 3; i++) {
        int task = t + i * 256;
        int r = task / 12;
        int c = task - r * 12;
        int n = m0 + r;
        __half2 hacc[4];
        hacc[0] = __half2half2(__float2half(0.f));
        hacc[1] = hacc[0]; hacc[2] = hacc[0]; hacc[3] = hacc[0];
        float acc[8] = {0.f, 0.f, 0.f, 0.f, 0.f, 0.f, 0.f, 0.f};
        if (n < N_NODES) {
            int2 od = g_od[n];
            int off = od.x, deg = od.y;
            int j = 0;
            for (; j + 3 < deg; j += 4) {
                int2 e0 = g_es[off + j];
                int2 e1 = g_es[off + j + 1];
                int2 e2 = g_es[off + j + 2];
                int2 e3 = g_es[off + j + 3];
                uint4 u0 = sup[(size_t)e0.x * 12 + c];
                uint4 u1 = sup[(size_t)e1.x * 12 + c];
                uint4 u2 = sup[(size_t)e2.x * 12 + c];
                uint4 u3 = sup[(size_t)e3.x * 12 + c];
                acc8h(hacc, u0, __float2half2_rn(__int_as_float(e0.y)));
                acc8h(hacc, u1, __float2half2_rn(__int_as_float(e1.y)));
                acc8h(hacc, u2, __float2half2_rn(__int_as_float(e2.y)));
                acc8h(hacc, u3, __float2half2_rn(__int_as_float(e3.y)));
            }
            for (; j < deg; j++) {
                int2 e0 = g_es[off + j];
                uint4 u0 = sup[(size_t)e0.x * 12 + c];
                acc8h(hacc, u0, __float2half2_rn(__int_as_float(e0.y)));
            }
            float2 f0 = __half22float2(hacc[0]);
            float2 f1 = __half22float2(hacc[1]);
            float2 f2 = __half22float2(hacc[2]);
            float2 f3 = __half22float2(hacc[3]);
            float4 bb0 = b1v[c * 2];
            float4 bb1 = b1v[c * 2 + 1];
            acc[0] = selu_f(f0.x + bb0.x); acc[1] = selu_f(f0.y + bb0.y);
            acc[2] = selu_f(f1.x + bb0.z); acc[3] = selu_f(f1.y + bb0.w);
            acc[4] = selu_f(f2.x + bb1.x); acc[5] = selu_f(f2.y + bb1.y);
            acc[6] = selu_f(f3.x + bb1.z); acc[7] = selu_f(f3.y + bb1.w);
        }
        uint4 val;
        val.x = h2u(__floats2half2_rn(acc[0], acc[1]));
        val.y = h2u(__floats2half2_rn(acc[2], acc[3]));
        val.z = h2u(__floats2half2_rn(acc[4], acc[5]));
        val.w = h2u(__floats2half2_rn(acc[6], acc[7]));
        *reinterpret_cast<uint4*>(
            reinterpret_cast<char*>(&As[0][0]) + r * 208 + c * 16) = val;
    }
    __syncthreads();

    // ---- Phase 2: support2[tile] = As[64x96] @ Bs ---------------------------
    const int lane = t & 31;
    const int wid = t >> 5;
    const int warp_m = wid >> 1;
    const int warp_n = wid & 1;
    const int lq = lane >> 2;
    const int lr = lane & 3;
    const unsigned as_base = (unsigned)__cvta_generic_to_shared(&As[0][0]);
    const unsigned bs_base = (unsigned)__cvta_generic_to_shared(&Bs[0][0]);

    float acc[4][4];
#pragma unroll
    for (int j = 0; j < 4; j++)
#pragma unroll
        for (int q = 0; q < 4; q++) acc[j][q] = 0.f;

#pragma unroll
    for (int ks = 0; ks < 6; ks++) {
        const int k16 = ks * 16;
        unsigned b[4][2];
        const int bl = lane & 15;
        const int brow = bl & 7;
        const int bk = k16 + ((bl >> 3) & 1) * 8;
#pragma unroll
        for (int j = 0; j < 4; j++) {
            unsigned addr = bs_base +
                (unsigned)((warp_n * 32 + j * 8 + brow) * 208 + bk * 2);
            ldsm_x2(addr, b[j][0], b[j][1]);
        }
        const int g = lane >> 3;
        const int rowl = lane & 7;
        const int ar_add = (g & 1) * 8 + rowl;
        const int ak = k16 + (g >> 1) * 8;
        unsigned a[4];
        unsigned addr = as_base +
            (unsigned)((warp_m * 16 + ar_add) * 208 + ak * 2);
        ldsm_x4(addr, a[0], a[1], a[2], a[3]);
#pragma unroll
        for (int j = 0; j < 4; j++) mma_f16(acc[j], a, b[j]);
    }

    int r0 = m0 + warp_m * 16 + lq;
#pragma unroll
    for (int j = 0; j < 4; j++) {
        int c0 = warp_n * 32 + j * 8 + 2 * lr;
        if (r0 < N_NODES)
            *reinterpret_cast<__half2*>(g_support2h + (size_t)r0 * 64 + c0) =
                __floats2half2_rn(acc[j][0], acc[j][1]);
        if (r0 + 8 < N_NODES)
            *reinterpret_cast<__half2*>(g_support2h + (size_t)(r0 + 8) * 64 + c0) =
                __floats2half2_rn(acc[j][2], acc[j][3]);
    }
}

// ---------------- K5: SpMM layer 2 (half2 acc) + pool + tail head ------------
__global__ __launch_bounds__(256)
void spmm2_final_kernel(const float* __restrict__ b2,
                        const float* __restrict__ sub, const float* __restrict__ Wf,
                        const float* __restrict__ bf, const float* __restrict__ gamma,
                        const float* __restrict__ beta, const float* __restrict__ mean,
                        const float* __restrict__ var, float* __restrict__ out) {
    __shared__ float sp[NCLASS];
    __shared__ int s_last;
    int t = threadIdx.x;
    if (t < NCLASS) sp[t] = 0.f;
    __syncthreads();

    int idx = blockIdx.x * 256 + t;
    int n = idx >> 3;          // 8 threads per node
    int c = t & 7;             // chunk of 8 halves
    float r[8] = {0.f, 0.f, 0.f, 0.f, 0.f, 0.f, 0.f, 0.f};

    if (n < N_NODES) {
        int2 od = g_od[n];
        int off = od.x, deg = od.y;
        const uint4* sup = reinterpret_cast<const uint4*>(g_support2h); // 8/row
        __half2 hacc[4];
        hacc[0] = __half2half2(__float2half(0.f));
        hacc[1] = hacc[0]; hacc[2] = hacc[0]; hacc[3] = hacc[0];
        int j = 0;
        for (; j + 3 < deg; j += 4) {
            int2 e0 = g_es[off + j];
            int2 e1 = g_es[off + j + 1];
            int2 e2 = g_es[off + j + 2];
            int2 e3 = g_es[off + j + 3];
            uint4 u0 = sup[(size_t)e0.x * 8 + c];
            uint4 u1 = sup[(size_t)e1.x * 8 + c];
            uint4 u2 = sup[(size_t)e2.x * 8 + c];
            uint4 u3 = sup[(size_t)e3.x * 8 + c];
            acc8h(hacc, u0, __float2half2_rn(__int_as_float(e0.y)));
            acc8h(hacc, u1, __float2half2_rn(__int_as_float(e1.y)));
            acc8h(hacc, u2, __float2half2_rn(__int_as_float(e2.y)));
            acc8h(hacc, u3, __float2half2_rn(__int_as_float(e3.y)));
        }
        for (; j < deg; j++) {
            int2 e0 = g_es[off + j];
            uint4 u0 = sup[(size_t)e0.x * 8 + c];
            acc8h(hacc, u0, __float2half2_rn(__int_as_float(e0.y)));
        }
        float2 f0 = __half22float2(hacc[0]);
        float2 f1 = __half22float2(hacc[1]);
        float2 f2 = __half22float2(hacc[2]);
        float2 f3 = __half22float2(hacc[3]);
        const float4* b2v = reinterpret_cast<const float4*>(b2);
        float4 bb0 = b2v[c * 2];
        float4 bb1 = b2v[c * 2 + 1];
        r[0] = selu_f(f0.x + bb0.x); r[1] = selu_f(f0.y + bb0.y);
        r[2] = selu_f(f1.x + bb0.z); r[3] = selu_f(f1.y + bb0.w);
        r[4] = selu_f(f2.x + bb1.x); r[5] = selu_f(f2.y + bb1.y);
        r[6] = selu_f(f3.x + bb1.z); r[7] = selu_f(f3.y + bb1.w);
    }

    // lanes t, t^8, t^16, t^24 share chunk c (different nodes)
#pragma unroll
    for (int q = 0; q < 8; q++) {
        r[q] += __shfl_xor_sync(0xffffffffu, r[q], 8);
        r[q] += __shfl_xor_sync(0xffffffffu, r[q], 16);
    }
    if ((t & 24) == 0) {
#pragma unroll
        for (int q = 0; q < 8; q++) atomicAdd(&sp[c * 8 + q], r[q]);
    }
    __syncthreads();
    if (t < NCLASS) atomicAdd(&g_pool[t], sp[t]);

    __threadfence();
    __syncthreads();
    if (t == 0) s_last = (atomicAdd(&g_done, 1) == (int)gridDim.x - 1);
    __syncthreads();
    if (!s_last) return;
    __threadfence();

    __shared__ float z[NCLASS + NEXT];
    __shared__ float logits[NCLASS];
    __shared__ float red[256];
    __shared__ float s_max, s_lse;

    if (t < NCLASS) {
        z[t] = selu_f(__ldcg(&g_pool[t]) / (float)N_NODES);
    } else if (t < NCLASS + NEXT) {
        int jj = t - NCLASS;
        z[t] = (sub[jj] - mean[jj]) * rsqrtf(var[jj] + BN_EPS) * gamma[jj] + beta[jj];
    }
    __syncthreads();

    if (t < NCLASS) {
        float a = bf[t];
        const float* wrow = Wf + (size_t)t * (NCLASS + NEXT);
#pragma unroll
        for (int k = 0; k < NCLASS + NEXT; k++) a += z[k] * wrow[k];
        logits[t] = a;
    }
    __syncthreads();

    if (t == 0) {
        float m = -INFINITY;
        for (int k = 0; k < NCLASS; k++) m = fmaxf(m, logits[k]);
        float s = 0.f;
        for (int k = 0; k < NCLASS; k++) s += expf(logits[k] - m);
        s_max = m;
        s_lse = logf(s);
    }
    __syncthreads();
    if (t < NCLASS) out[t] = logits[t] - s_max - s_lse;

    float l = 0.f;
    const int TOTW = NCLASS * (NCLASS + NEXT);
    for (int i = t; i < TOTW; i += 256) l += fabsf(Wf[i]);
    red[t] = l;
    __syncthreads();
    for (int s2 = 128; s2 > 0; s2 >>= 1) {
        if (t < s2) red[t] += red[t + s2];
        __syncthreads();
    }
    if (t == 0) out[NCLASS] = red[0] / (float)TOTW;

    // restore invariants
    if (t < NCLASS) g_pool[t] = 0.f;
    if (t == 0) { g_done = 0; g_total = 0; }
}

// ---------------- launch -----------------------------------------------------
extern "C" void kernel_launch(void* const* d_in, const int* in_sizes, int n_in,
                              void* d_out, int out_size) {
    const float* x     = (const float*)d_in[0];
    const int*   row   = (const int*)  d_in[1];
    const int*   col   = (const int*)  d_in[2];
    const float* ew    = (const float*)d_in[3];
    const float* sub   = (const float*)d_in[4];
    const float* W1    = (const float*)d_in[5];
    const float* b1    = (const float*)d_in[6];
    const float* W2    = (const float*)d_in[7];
    const float* b2    = (const float*)d_in[8];
    const float* Wf    = (const float*)d_in[9];
    const float* bf    = (const float*)d_in[10];
    const float* gamma = (const float*)d_in[11];
    const float* beta  = (const float*)d_in[12];
    const float* mean  = (const float*)d_in[13];
    const float* var   = (const float*)d_in[14];
    float* out = (float*)d_out;

    const int E = (n_in > 1) ? in_sizes[1] : N_EDGES;

    const int GB  = (N_NODES + 127) / 128;   // 391 gemm1 tile blocks
    const int MB  = (N_NODES + 63) / 64;     // 782 mid tile blocks
    const int SCB = (E + 1023) / 1024;       // scatter blocks

    hist_kernel<<<(E + 255) / 256, 256>>>(row, E);
    alloc_kernel<<<(N_NODES + 255) / 256, 256>>>();
    fat1_kernel<<<GB + SCB, 256>>>(x, W1, row, col, ew, E, GB);
    mid_kernel<<<MB, 256>>>(b1, W2);
    spmm2_final_kernel<<<(N_NODES * 8 + 255) / 256, 256>>>(
        b2, sub, Wf, bf, gamma, beta, mean, var, out);
}